// round 1
// baseline (speedup 1.0000x reference)
#include <cuda_runtime.h>
#include <math.h>

// Problem constants
#define Bn   4
#define Ss   512
#define Dd   512
#define Hh   8
#define DKk  64
#define Nl   6
#define Vv   32000
#define FFf  2048
#define TOK  (Bn*Ss)   // 2048 tokens per sequence-set

// ---------------- scratch (static __device__, no allocations) ----------------
__device__ float g_x[TOK*Dd];
__device__ float g_y[TOK*Dd];
__device__ float g_q[TOK*Dd];
__device__ float g_k[TOK*Dd];
__device__ float g_v[TOK*Dd];
__device__ float g_attn[TOK*Dd];
__device__ float g_tmp[TOK*Dd];
__device__ float g_ffn[TOK*FFf];
__device__ float g_scores[(size_t)Bn*Hh*Ss*Ss];

// ---------------- GEMM: C = alpha * A(MxK) * B(KxN or NxK if TRANSB) + bias ----
// Batched via blockIdx.z: offset = (z / Hsub) * strideOuter + (z % Hsub) * strideInner
#define BM 64
#define BN 64
#define BKd 16

template<bool TRANSB>
__global__ __launch_bounds__(256)
void gemm_kernel(const float* __restrict__ A, const float* __restrict__ Bm,
                 const float* __restrict__ bias, float* __restrict__ C,
                 int M, int N, int K, int lda, int ldb, int ldc,
                 long long sAo, long long sAi, long long sBo, long long sBi,
                 long long sCo, long long sCi, int Hsub,
                 float alpha, int doBias, int doRelu)
{
    __shared__ float As[BKd][BM + 4];
    __shared__ float Bs[BKd][TRANSB ? (BN + 4) : BN];

    int z = blockIdx.z;
    int zo = z / Hsub, zi = z % Hsub;
    const float* Ab = A + zo * sAo + zi * sAi;
    const float* Bb = Bm + zo * sBo + zi * sBi;
    float* Cb = C + zo * sCo + zi * sCi;

    int tid = threadIdx.x;           // 256 threads
    int tx = tid & 15, ty = tid >> 4;
    int row0 = blockIdx.y * BM;
    int col0 = blockIdx.x * BN;

    float acc[4][4];
#pragma unroll
    for (int i = 0; i < 4; i++)
#pragma unroll
        for (int j = 0; j < 4; j++) acc[i][j] = 0.f;

    for (int k0 = 0; k0 < K; k0 += BKd) {
        // Load A tile transposed: As[k][m]
        {
            int ac = tid & 15, ar = tid >> 4;   // ac: k, ar: m-base
#pragma unroll
            for (int i = 0; i < 4; i++)
                As[ac][ar + 16*i] = Ab[(long long)(row0 + ar + 16*i) * lda + (k0 + ac)];
        }
        if (TRANSB) {
            // B is (N x K) row-major; Bs[k][n]
            int bc = tid & 15, br = tid >> 4;
#pragma unroll
            for (int i = 0; i < 4; i++)
                Bs[bc][br + 16*i] = Bb[(long long)(col0 + br + 16*i) * ldb + (k0 + bc)];
        } else {
            // B is (K x N) row-major; Bs[k][n]
            int bc = tid & 63, br = tid >> 6;
#pragma unroll
            for (int i = 0; i < 4; i++)
                Bs[br + 4*i][bc] = Bb[(long long)(k0 + br + 4*i) * ldb + (col0 + bc)];
        }
        __syncthreads();
#pragma unroll
        for (int kk = 0; kk < BKd; kk++) {
            float4 av = *reinterpret_cast<const float4*>(&As[kk][ty * 4]);
            float4 bv = *reinterpret_cast<const float4*>(&Bs[kk][tx * 4]);
            float a[4] = {av.x, av.y, av.z, av.w};
            float b[4] = {bv.x, bv.y, bv.z, bv.w};
#pragma unroll
            for (int i = 0; i < 4; i++)
#pragma unroll
                for (int j = 0; j < 4; j++)
                    acc[i][j] += a[i] * b[j];
        }
        __syncthreads();
    }

#pragma unroll
    for (int i = 0; i < 4; i++) {
        int r = row0 + ty * 4 + i;
#pragma unroll
        for (int j = 0; j < 4; j++) {
            int c = col0 + tx * 4 + j;
            float v = acc[i][j] * alpha;
            if (doBias) v += bias[c];
            if (doRelu) v = fmaxf(v, 0.f);
            Cb[(long long)r * ldc + c] = v;
        }
    }
}

// ---------------- softmax over last dim (in-place), optional causal ----------
__global__ __launch_bounds__(256)
void softmax_rows(float* __restrict__ P, int L, int causal)
{
    long long row = blockIdx.x;
    float* p = P + row * (long long)L;
    int qpos = (int)(row % Ss);
    int t = threadIdx.x;
    __shared__ float red[256];

    float mx = -3.0e38f;
    for (int k = t; k < L; k += 256) {
        float v = p[k];
        if (causal && k > qpos) v = -1e9f;
        mx = fmaxf(mx, v);
    }
    red[t] = mx; __syncthreads();
    for (int o = 128; o; o >>= 1) { if (t < o) red[t] = fmaxf(red[t], red[t + o]); __syncthreads(); }
    mx = red[0]; __syncthreads();

    float sum = 0.f;
    for (int k = t; k < L; k += 256) {
        float v = p[k];
        if (causal && k > qpos) v = -1e9f;
        float e = __expf(v - mx);
        p[k] = e;
        sum += e;
    }
    red[t] = sum; __syncthreads();
    for (int o = 128; o; o >>= 1) { if (t < o) red[t] += red[t + o]; __syncthreads(); }
    float inv = 1.0f / red[0];
    for (int k = t; k < L; k += 256) p[k] *= inv;
}

// ---------------- x = LayerNorm(x + sub), D = 512, no affine --------------------
__global__ __launch_bounds__(256)
void add_ln_kernel(float* __restrict__ x, const float* __restrict__ sub)
{
    int row = blockIdx.x;
    float* xr = x + (long long)row * Dd;
    const float* sr = sub + (long long)row * Dd;
    int t = threadIdx.x;
    __shared__ float red[256];

    float v0 = xr[t] + sr[t];
    float v1 = xr[t + 256] + sr[t + 256];
    red[t] = v0 + v1; __syncthreads();
    for (int o = 128; o; o >>= 1) { if (t < o) red[t] += red[t + o]; __syncthreads(); }
    float mu = red[0] * (1.0f / 512.0f); __syncthreads();
    float d0 = v0 - mu, d1 = v1 - mu;
    red[t] = d0 * d0 + d1 * d1; __syncthreads();
    for (int o = 128; o; o >>= 1) { if (t < o) red[t] += red[t + o]; __syncthreads(); }
    float inv = rsqrtf(red[0] * (1.0f / 512.0f) + 1e-5f);
    xr[t] = d0 * inv;
    xr[t + 256] = d1 * inv;
}

// ---------------- embedding lookup + positional encoding ----------------------
__global__ __launch_bounds__(512)
void embed_pe_kernel(const int* __restrict__ tok, const float* __restrict__ emb,
                     float* __restrict__ out)
{
    int idx = blockIdx.x;      // token index b*S+s
    int s = idx % Ss;
    int j = threadIdx.x;       // 0..511
    int tk = tok[idx];
    float ang = (float)s * powf(10000.0f, -2.0f * (float)j / 512.0f);
    float pe = (j & 1) ? cosf(ang) : sinf(ang);
    out[(long long)idx * Dd + j] = emb[(long long)tk * Dd + j] + pe;
}

// ---------------- host orchestration ------------------------------------------
static float* sym(float* /*dummy tag*/, const void* symaddr) { return nullptr; } // unused

static void gemm_plain(const float* A, const float* B, const float* bias, float* C,
                       int M, int N, int K, int lda, int ldb, int ldc,
                       bool doBias, bool doRelu)
{
    dim3 g(N / 64, M / 64, 1);
    gemm_kernel<false><<<g, 256>>>(A, B, bias, C, M, N, K, lda, ldb, ldc,
                                   0, 0, 0, 0, 0, 0, 1, 1.0f,
                                   doBias ? 1 : 0, doRelu ? 1 : 0);
}

static void run_mha(const float* xq, const float* xkv, const float* w, float* out,
                    bool causal,
                    float* q, float* k, float* v, float* attn, float* scores)
{
    const long long DDl = (long long)Dd * Dd;
    gemm_plain(xq,  w + 0 * DDl, nullptr, q, TOK, Dd, Dd, Dd, Dd, Dd, false, false);
    gemm_plain(xkv, w + 1 * DDl, nullptr, k, TOK, Dd, Dd, Dd, Dd, Dd, false, false);
    gemm_plain(xkv, w + 2 * DDl, nullptr, v, TOK, Dd, Dd, Dd, Dd, Dd, false, false);

    // scores[b,h,q,k] = (Q . K) / 8, batched NT GEMM over 32 (b,h) pairs
    {
        dim3 g(Ss / 64, Ss / 64, Bn * Hh);
        gemm_kernel<true><<<g, 256>>>(q, k, nullptr, scores,
            Ss, Ss, DKk, Dd, Dd, Ss,
            (long long)Ss * Dd, DKk,                 // A: per-b, per-h
            (long long)Ss * Dd, DKk,                 // B: per-b, per-h
            (long long)Hh * Ss * Ss, (long long)Ss * Ss,  // C
            Hh, 0.125f, 0, 0);
    }
    softmax_rows<<<Bn * Hh * Ss, 256>>>(scores, Ss, causal ? 1 : 0);

    // attn[b,q,h,:] = scores @ V, batched NN GEMM
    {
        dim3 g(DKk / 64, Ss / 64, Bn * Hh);
        gemm_kernel<false><<<g, 256>>>(scores, v, nullptr, attn,
            Ss, DKk, Ss, Ss, Dd, Dd,
            (long long)Hh * Ss * Ss, (long long)Ss * Ss,
            (long long)Ss * Dd, DKk,
            (long long)Ss * Dd, DKk,
            Hh, 1.0f, 0, 0);
    }
    gemm_plain(attn, w + 3 * DDl, nullptr, out, TOK, Dd, Dd, Dd, Dd, Dd, false, false);
}

extern "C" void kernel_launch(void* const* d_in, const int* in_sizes, int n_in,
                              void* d_out, int out_size)
{
    const int*   src          = (const int*)  d_in[0];
    const int*   trg          = (const int*)  d_in[1];
    const float* src_emb      = (const float*)d_in[2];
    const float* trg_emb      = (const float*)d_in[3];
    const float* enc_qkvo     = (const float*)d_in[4];
    const float* enc_ffn_w1   = (const float*)d_in[5];
    const float* enc_ffn_b1   = (const float*)d_in[6];
    const float* enc_ffn_w2   = (const float*)d_in[7];
    const float* enc_ffn_b2   = (const float*)d_in[8];
    const float* dec_self_qkvo= (const float*)d_in[9];
    const float* dec_cross_qkvo=(const float*)d_in[10];
    const float* dec_ffn_w1   = (const float*)d_in[11];
    const float* dec_ffn_b1   = (const float*)d_in[12];
    const float* dec_ffn_w2   = (const float*)d_in[13];
    const float* dec_ffn_b2   = (const float*)d_in[14];
    const float* out_w        = (const float*)d_in[15];
    const float* out_b        = (const float*)d_in[16];
    float* out = (float*)d_out;

    float *x, *y, *q, *k, *v, *attn, *tmp, *ffn, *scores;
    cudaGetSymbolAddress((void**)&x,      g_x);
    cudaGetSymbolAddress((void**)&y,      g_y);
    cudaGetSymbolAddress((void**)&q,      g_q);
    cudaGetSymbolAddress((void**)&k,      g_k);
    cudaGetSymbolAddress((void**)&v,      g_v);
    cudaGetSymbolAddress((void**)&attn,   g_attn);
    cudaGetSymbolAddress((void**)&tmp,    g_tmp);
    cudaGetSymbolAddress((void**)&ffn,    g_ffn);
    cudaGetSymbolAddress((void**)&scores, g_scores);

    // Embeddings + positional encodings
    embed_pe_kernel<<<TOK, 512>>>(src, src_emb, x);
    embed_pe_kernel<<<TOK, 512>>>(trg, trg_emb, y);

    const long long DDl = (long long)Dd * Dd;

    // ---------------- Encoder stack ----------------
    for (int i = 0; i < Nl; i++) {
        run_mha(x, x, enc_qkvo + (long long)i * 4 * DDl, tmp, false,
                q, k, v, attn, scores);
        add_ln_kernel<<<TOK, 256>>>(x, tmp);

        gemm_plain(x, enc_ffn_w1 + (long long)i * Dd * FFf,
                   enc_ffn_b1 + (long long)i * FFf, ffn,
                   TOK, FFf, Dd, Dd, FFf, FFf, true, true);
        gemm_plain(ffn, enc_ffn_w2 + (long long)i * FFf * Dd,
                   enc_ffn_b2 + (long long)i * Dd, tmp,
                   TOK, Dd, FFf, FFf, Dd, Dd, true, false);
        add_ln_kernel<<<TOK, 256>>>(x, tmp);
    }

    // ---------------- Decoder stack ----------------
    for (int i = 0; i < Nl; i++) {
        run_mha(y, y, dec_self_qkvo + (long long)i * 4 * DDl, tmp, true,
                q, k, v, attn, scores);
        add_ln_kernel<<<TOK, 256>>>(y, tmp);

        run_mha(y, x, dec_cross_qkvo + (long long)i * 4 * DDl, tmp, false,
                q, k, v, attn, scores);
        add_ln_kernel<<<TOK, 256>>>(y, tmp);

        gemm_plain(y, dec_ffn_w1 + (long long)i * Dd * FFf,
                   dec_ffn_b1 + (long long)i * FFf, ffn,
                   TOK, FFf, Dd, Dd, FFf, FFf, true, true);
        gemm_plain(ffn, dec_ffn_w2 + (long long)i * FFf * Dd,
                   dec_ffn_b2 + (long long)i * Dd, tmp,
                   TOK, Dd, FFf, FFf, Dd, Dd, true, false);
        add_ln_kernel<<<TOK, 256>>>(y, tmp);
    }

    // ---------------- Output projection + vocab softmax ----------------
    gemm_plain(y, out_w, out_b, out, TOK, Vv, Dd, Dd, Vv, Vv, true, false);
    softmax_rows<<<TOK, 256>>>(out, Vv, 0);
}

// round 2
// speedup vs baseline: 1.7813x; 1.7813x over previous
#include <cuda_runtime.h>
#include <cuda_bf16.h>
#include <math.h>
#include <stdint.h>

// Problem constants
#define Bn   4
#define Ss   512
#define Dd   512
#define Hh   8
#define DKk  64
#define Nl   6
#define Vv   32000
#define FFf  2048
#define TOK  (Bn*Ss)

// ---------------- scratch ----------------
__device__ float g_x[TOK*Dd];
__device__ float g_y[TOK*Dd];
__device__ float g_q[TOK*Dd];
__device__ float g_k[TOK*Dd];
__device__ float g_v[TOK*Dd];
__device__ float g_attn[TOK*Dd];
__device__ float g_tmp[TOK*Dd];
__device__ float g_ffn[TOK*FFf];
__device__ float g_scores[(size_t)Bn*Hh*Ss*Ss];

// ---------------- bf16 split helpers ----------------
// pack two floats (x0 = lower k index, x1 = upper) into bf16x2 hi & residual lo
__device__ __forceinline__ void cvt_pair(float x0, float x1, uint32_t& hi, uint32_t& lo)
{
    uint32_t h;
    asm("cvt.rn.bf16x2.f32 %0, %1, %2;" : "=r"(h) : "f"(x1), "f"(x0));
    __nv_bfloat162 hb = *reinterpret_cast<__nv_bfloat162*>(&h);
    float r0 = x0 - __bfloat162float(hb.x);
    float r1 = x1 - __bfloat162float(hb.y);
    uint32_t l;
    asm("cvt.rn.bf16x2.f32 %0, %1, %2;" : "=r"(l) : "f"(r1), "f"(r0));
    hi = h; lo = l;
}

__device__ __forceinline__ void mma16816(float* c, const uint32_t* a, const uint32_t* b)
{
    asm volatile(
        "mma.sync.aligned.m16n8k16.row.col.f32.bf16.bf16.f32 "
        "{%0,%1,%2,%3}, {%4,%5,%6,%7}, {%8,%9}, {%0,%1,%2,%3};\n"
        : "+f"(c[0]), "+f"(c[1]), "+f"(c[2]), "+f"(c[3])
        : "r"(a[0]), "r"(a[1]), "r"(a[2]), "r"(a[3]), "r"(b[0]), "r"(b[1]));
}

// ---------------- GEMM: C = alpha * A(MxK) * B(KxN or NxK if TRANSB) + bias ----
// bf16x3 emulation of fp32 GEMM on tensor cores.
// Template: tile TBMxTBN, NTHREADS, warps arranged WARPS_M x (WARPS/WARPS_M)
template<int TBM, int TBN, int NTHREADS, int WARPS_M, bool TRANSB>
__global__ __launch_bounds__(NTHREADS)
void gemm_mma(const float* __restrict__ A, const float* __restrict__ Bm,
              const float* __restrict__ bias, float* __restrict__ C,
              int M, int N, int K, int lda, int ldb, int ldc,
              long long sAo, long long sAi, long long sBo, long long sBi,
              long long sCo, long long sCi, int Hsub,
              float alpha, int doBias, int doRelu)
{
    constexpr int WARPS   = NTHREADS / 32;
    constexpr int WARPS_N = WARPS / WARPS_M;
    constexpr int WM = TBM / WARPS_M;       // warp tile M
    constexpr int WN = TBN / WARPS_N;       // warp tile N
    constexpr int MT = WM / 16;             // m16 tiles per warp
    constexpr int NT = WN / 8;              // n8 tiles per warp
    constexpr int AS = TBM + 8;             // smem stride (uint32 units)
    constexpr int BS = TBN + 8;

    __shared__ uint32_t Ah[16 * AS];
    __shared__ uint32_t Al[16 * AS];
    __shared__ uint32_t Bh[16 * BS];
    __shared__ uint32_t Bl[16 * BS];

    int z = blockIdx.z;
    int zo = z / Hsub, zi = z % Hsub;
    const float* Ab = A  + zo * sAo + zi * sAi;
    const float* Bb = Bm + zo * sBo + zi * sBi;
    float*       Cb = C  + zo * sCo + zi * sCi;

    int tid = threadIdx.x;
    int wid = tid >> 5, lane = tid & 31;
    int wm = wid % WARPS_M, wn = wid / WARPS_M;
    int group = lane >> 2, tig = lane & 3;

    int row0 = blockIdx.x * TBM;
    int col0 = blockIdx.y * TBN;

    float acc[MT][NT][4];
#pragma unroll
    for (int i = 0; i < MT; i++)
#pragma unroll
        for (int j = 0; j < NT; j++)
#pragma unroll
            for (int t = 0; t < 4; t++) acc[i][j][t] = 0.f;

    for (int k0 = 0; k0 < K; k0 += 32) {
        // ---- load A tile (TBM x 32, row-major) ----
        constexpr int AF4 = TBM * 8 / NTHREADS;
#pragma unroll
        for (int i = 0; i < AF4; i++) {
            int idx = tid + i * NTHREADS;
            int r = idx >> 3, c4 = idx & 7;
            float4 v = *reinterpret_cast<const float4*>(
                Ab + (long long)(row0 + r) * lda + k0 + c4 * 4);
            uint32_t h0, l0, h1, l1;
            cvt_pair(v.x, v.y, h0, l0);
            cvt_pair(v.z, v.w, h1, l1);
            Ah[(c4 * 2    ) * AS + r] = h0;  Al[(c4 * 2    ) * AS + r] = l0;
            Ah[(c4 * 2 + 1) * AS + r] = h1;  Al[(c4 * 2 + 1) * AS + r] = l1;
        }
        // ---- load B tile ----
        if (TRANSB) {
            // B is N x K row-major: rows = n, cols = k
            constexpr int BF4 = TBN * 8 / NTHREADS;
#pragma unroll
            for (int i = 0; i < BF4; i++) {
                int idx = tid + i * NTHREADS;
                int n = idx >> 3, c4 = idx & 7;
                float4 v = *reinterpret_cast<const float4*>(
                    Bb + (long long)(col0 + n) * ldb + k0 + c4 * 4);
                uint32_t h0, l0, h1, l1;
                cvt_pair(v.x, v.y, h0, l0);
                cvt_pair(v.z, v.w, h1, l1);
                Bh[(c4 * 2    ) * BS + n] = h0;  Bl[(c4 * 2    ) * BS + n] = l0;
                Bh[(c4 * 2 + 1) * BS + n] = h1;  Bl[(c4 * 2 + 1) * BS + n] = l1;
            }
        } else {
            // B is K x N row-major
            constexpr int BLD = 16 * (TBN / 4) / NTHREADS;
#pragma unroll
            for (int i = 0; i < BLD; i++) {
                int idx = tid + i * NTHREADS;
                int kp = idx / (TBN / 4), n4 = idx % (TBN / 4);
                const float* p = Bb + (long long)(k0 + 2 * kp) * ldb + col0 + n4 * 4;
                float4 r0 = *reinterpret_cast<const float4*>(p);
                float4 r1 = *reinterpret_cast<const float4*>(p + ldb);
                uint32_t h, l;
                cvt_pair(r0.x, r1.x, h, l); Bh[kp * BS + n4 * 4 + 0] = h; Bl[kp * BS + n4 * 4 + 0] = l;
                cvt_pair(r0.y, r1.y, h, l); Bh[kp * BS + n4 * 4 + 1] = h; Bl[kp * BS + n4 * 4 + 1] = l;
                cvt_pair(r0.z, r1.z, h, l); Bh[kp * BS + n4 * 4 + 2] = h; Bl[kp * BS + n4 * 4 + 2] = l;
                cvt_pair(r0.w, r1.w, h, l); Bh[kp * BS + n4 * 4 + 3] = h; Bl[kp * BS + n4 * 4 + 3] = l;
            }
        }
        __syncthreads();

        // ---- compute: 2 k-steps of 16 ----
#pragma unroll
        for (int ks = 0; ks < 2; ks++) {
            uint32_t ah[MT][4], al[MT][4], bh[NT][2], bl[NT][2];
#pragma unroll
            for (int mt = 0; mt < MT; mt++) {
                int r = wm * WM + mt * 16 + group;
                int kp0 = ks * 8 + tig, kp1 = kp0 + 4;
                ah[mt][0] = Ah[kp0 * AS + r];     al[mt][0] = Al[kp0 * AS + r];
                ah[mt][1] = Ah[kp0 * AS + r + 8]; al[mt][1] = Al[kp0 * AS + r + 8];
                ah[mt][2] = Ah[kp1 * AS + r];     al[mt][2] = Al[kp1 * AS + r];
                ah[mt][3] = Ah[kp1 * AS + r + 8]; al[mt][3] = Al[kp1 * AS + r + 8];
            }
#pragma unroll
            for (int nt = 0; nt < NT; nt++) {
                int c = wn * WN + nt * 8 + group;
                int kp0 = ks * 8 + tig, kp1 = kp0 + 4;
                bh[nt][0] = Bh[kp0 * BS + c];  bl[nt][0] = Bl[kp0 * BS + c];
                bh[nt][1] = Bh[kp1 * BS + c];  bl[nt][1] = Bl[kp1 * BS + c];
            }
#pragma unroll
            for (int mt = 0; mt < MT; mt++)
#pragma unroll
                for (int nt = 0; nt < NT; nt++) {
                    mma16816(acc[mt][nt], ah[mt], bh[nt]);
                    mma16816(acc[mt][nt], al[mt], bh[nt]);
                    mma16816(acc[mt][nt], ah[mt], bl[nt]);
                }
        }
        __syncthreads();
    }

    // ---- epilogue ----
#pragma unroll
    for (int mt = 0; mt < MT; mt++) {
        int r = row0 + wm * WM + mt * 16 + group;
#pragma unroll
        for (int nt = 0; nt < NT; nt++) {
            int c = col0 + wn * WN + nt * 8 + tig * 2;
            float v00 = acc[mt][nt][0] * alpha;
            float v01 = acc[mt][nt][1] * alpha;
            float v10 = acc[mt][nt][2] * alpha;
            float v11 = acc[mt][nt][3] * alpha;
            if (doBias) {
                float2 bb = *reinterpret_cast<const float2*>(&bias[c]);
                v00 += bb.x; v01 += bb.y; v10 += bb.x; v11 += bb.y;
            }
            if (doRelu) {
                v00 = fmaxf(v00, 0.f); v01 = fmaxf(v01, 0.f);
                v10 = fmaxf(v10, 0.f); v11 = fmaxf(v11, 0.f);
            }
            *reinterpret_cast<float2*>(&Cb[(long long)r * ldc + c])       = make_float2(v00, v01);
            *reinterpret_cast<float2*>(&Cb[(long long)(r + 8) * ldc + c]) = make_float2(v10, v11);
        }
    }
}

// ---------------- softmax over last dim (in-place), optional causal ----------
__global__ __launch_bounds__(256)
void softmax_rows(float* __restrict__ P, int L, int causal)
{
    long long row = blockIdx.x;
    float* p = P + row * (long long)L;
    int qpos = (int)(row % Ss);
    int t = threadIdx.x;
    __shared__ float red[256];

    float mx = -3.0e38f;
    for (int k = t; k < L; k += 256) {
        float v = p[k];
        if (causal && k > qpos) v = -1e9f;
        mx = fmaxf(mx, v);
    }
    red[t] = mx; __syncthreads();
    for (int o = 128; o; o >>= 1) { if (t < o) red[t] = fmaxf(red[t], red[t + o]); __syncthreads(); }
    mx = red[0]; __syncthreads();

    float sum = 0.f;
    for (int k = t; k < L; k += 256) {
        float v = p[k];
        if (causal && k > qpos) v = -1e9f;
        float e = __expf(v - mx);
        p[k] = e;
        sum += e;
    }
    red[t] = sum; __syncthreads();
    for (int o = 128; o; o >>= 1) { if (t < o) red[t] += red[t + o]; __syncthreads(); }
    float inv = 1.0f / red[0];
    for (int k = t; k < L; k += 256) p[k] *= inv;
}

// ---------------- x = LayerNorm(x + sub) --------------------
__global__ __launch_bounds__(256)
void add_ln_kernel(float* __restrict__ x, const float* __restrict__ sub)
{
    int row = blockIdx.x;
    float* xr = x + (long long)row * Dd;
    const float* sr = sub + (long long)row * Dd;
    int t = threadIdx.x;
    __shared__ float red[256];

    float v0 = xr[t] + sr[t];
    float v1 = xr[t + 256] + sr[t + 256];
    red[t] = v0 + v1; __syncthreads();
    for (int o = 128; o; o >>= 1) { if (t < o) red[t] += red[t + o]; __syncthreads(); }
    float mu = red[0] * (1.0f / 512.0f); __syncthreads();
    float d0 = v0 - mu, d1 = v1 - mu;
    red[t] = d0 * d0 + d1 * d1; __syncthreads();
    for (int o = 128; o; o >>= 1) { if (t < o) red[t] += red[t + o]; __syncthreads(); }
    float inv = rsqrtf(red[0] * (1.0f / 512.0f) + 1e-5f);
    xr[t] = d0 * inv;
    xr[t + 256] = d1 * inv;
}

// ---------------- embedding + positional encoding ----------------
__global__ __launch_bounds__(512)
void embed_pe_kernel(const int* __restrict__ tok, const float* __restrict__ emb,
                     float* __restrict__ out)
{
    int idx = blockIdx.x;
    int s = idx % Ss;
    int j = threadIdx.x;
    int tk = tok[idx];
    float ang = (float)s * powf(10000.0f, -2.0f * (float)j / 512.0f);
    float pe = (j & 1) ? cosf(ang) : sinf(ang);
    out[(long long)idx * Dd + j] = emb[(long long)tk * Dd + j] + pe;
}

// ---------------- host orchestration ------------------------------------------
static void gemm64(const float* A, const float* B, const float* bias, float* C,
                   int M, int N, int K, int lda, int ldb, int ldc,
                   bool doBias, bool doRelu)
{
    dim3 g(M / 64, N / 64, 1);
    gemm_mma<64, 64, 128, 2, false><<<g, 128>>>(A, B, bias, C, M, N, K, lda, ldb, ldc,
        0, 0, 0, 0, 0, 0, 1, 1.0f, doBias ? 1 : 0, doRelu ? 1 : 0);
}

static void gemm128(const float* A, const float* B, const float* bias, float* C,
                    int M, int N, int K, int lda, int ldb, int ldc,
                    bool doBias, bool doRelu)
{
    dim3 g(M / 128, N / 128, 1);
    gemm_mma<128, 128, 256, 4, false><<<g, 256>>>(A, B, bias, C, M, N, K, lda, ldb, ldc,
        0, 0, 0, 0, 0, 0, 1, 1.0f, doBias ? 1 : 0, doRelu ? 1 : 0);
}

static void run_mha(const float* xq, const float* xkv, const float* w, float* out,
                    bool causal,
                    float* q, float* k, float* v, float* attn, float* scores)
{
    const long long DDl = (long long)Dd * Dd;
    gemm64(xq,  w + 0 * DDl, nullptr, q, TOK, Dd, Dd, Dd, Dd, Dd, false, false);
    gemm64(xkv, w + 1 * DDl, nullptr, k, TOK, Dd, Dd, Dd, Dd, Dd, false, false);
    gemm64(xkv, w + 2 * DDl, nullptr, v, TOK, Dd, Dd, Dd, Dd, Dd, false, false);

    // scores = Q @ K^T / 8, batched over 32 (b,h)
    {
        dim3 g(Ss / 64, Ss / 64, Bn * Hh);
        gemm_mma<64, 64, 128, 2, true><<<g, 128>>>(q, k, nullptr, scores,
            Ss, Ss, DKk, Dd, Dd, Ss,
            (long long)Ss * Dd, DKk,
            (long long)Ss * Dd, DKk,
            (long long)Hh * Ss * Ss, (long long)Ss * Ss,
            Hh, 0.125f, 0, 0);
    }
    softmax_rows<<<Bn * Hh * Ss, 256>>>(scores, Ss, causal ? 1 : 0);

    // attn = P @ V, batched
    {
        dim3 g(Ss / 64, DKk / 64, Bn * Hh);
        gemm_mma<64, 64, 128, 2, false><<<g, 128>>>(scores, v, nullptr, attn,
            Ss, DKk, Ss, Ss, Dd, Dd,
            (long long)Hh * Ss * Ss, (long long)Ss * Ss,
            (long long)Ss * Dd, DKk,
            (long long)Ss * Dd, DKk,
            Hh, 1.0f, 0, 0);
    }
    gemm64(attn, w + 3 * DDl, nullptr, out, TOK, Dd, Dd, Dd, Dd, Dd, false, false);
}

extern "C" void kernel_launch(void* const* d_in, const int* in_sizes, int n_in,
                              void* d_out, int out_size)
{
    const int*   src           = (const int*)  d_in[0];
    const int*   trg           = (const int*)  d_in[1];
    const float* src_emb       = (const float*)d_in[2];
    const float* trg_emb       = (const float*)d_in[3];
    const float* enc_qkvo      = (const float*)d_in[4];
    const float* enc_ffn_w1    = (const float*)d_in[5];
    const float* enc_ffn_b1    = (const float*)d_in[6];
    const float* enc_ffn_w2    = (const float*)d_in[7];
    const float* enc_ffn_b2    = (const float*)d_in[8];
    const float* dec_self_qkvo = (const float*)d_in[9];
    const float* dec_cross_qkvo= (const float*)d_in[10];
    const float* dec_ffn_w1    = (const float*)d_in[11];
    const float* dec_ffn_b1    = (const float*)d_in[12];
    const float* dec_ffn_w2    = (const float*)d_in[13];
    const float* dec_ffn_b2    = (const float*)d_in[14];
    const float* out_w         = (const float*)d_in[15];
    const float* out_b         = (const float*)d_in[16];
    float* out = (float*)d_out;

    float *x, *y, *q, *k, *v, *attn, *tmp, *ffn, *scores;
    cudaGetSymbolAddress((void**)&x,      g_x);
    cudaGetSymbolAddress((void**)&y,      g_y);
    cudaGetSymbolAddress((void**)&q,      g_q);
    cudaGetSymbolAddress((void**)&k,      g_k);
    cudaGetSymbolAddress((void**)&v,      g_v);
    cudaGetSymbolAddress((void**)&attn,   g_attn);
    cudaGetSymbolAddress((void**)&tmp,    g_tmp);
    cudaGetSymbolAddress((void**)&ffn,    g_ffn);
    cudaGetSymbolAddress((void**)&scores, g_scores);

    embed_pe_kernel<<<TOK, 512>>>(src, src_emb, x);
    embed_pe_kernel<<<TOK, 512>>>(trg, trg_emb, y);

    const long long DDl = (long long)Dd * Dd;

    // ---------------- Encoder ----------------
    for (int i = 0; i < Nl; i++) {
        run_mha(x, x, enc_qkvo + (long long)i * 4 * DDl, tmp, false,
                q, k, v, attn, scores);
        add_ln_kernel<<<TOK, 256>>>(x, tmp);

        gemm128(x, enc_ffn_w1 + (long long)i * Dd * FFf,
                enc_ffn_b1 + (long long)i * FFf, ffn,
                TOK, FFf, Dd, Dd, FFf, FFf, true, true);
        gemm64(ffn, enc_ffn_w2 + (long long)i * FFf * Dd,
               enc_ffn_b2 + (long long)i * Dd, tmp,
               TOK, Dd, FFf, FFf, Dd, Dd, true, false);
        add_ln_kernel<<<TOK, 256>>>(x, tmp);
    }

    // ---------------- Decoder ----------------
    for (int i = 0; i < Nl; i++) {
        run_mha(y, y, dec_self_qkvo + (long long)i * 4 * DDl, tmp, true,
                q, k, v, attn, scores);
        add_ln_kernel<<<TOK, 256>>>(y, tmp);

        run_mha(y, x, dec_cross_qkvo + (long long)i * 4 * DDl, tmp, false,
                q, k, v, attn, scores);
        add_ln_kernel<<<TOK, 256>>>(y, tmp);

        gemm128(y, dec_ffn_w1 + (long long)i * Dd * FFf,
                dec_ffn_b1 + (long long)i * FFf, ffn,
                TOK, FFf, Dd, Dd, FFf, FFf, true, true);
        gemm64(ffn, dec_ffn_w2 + (long long)i * FFf * Dd,
               dec_ffn_b2 + (long long)i * Dd, tmp,
               TOK, Dd, FFf, FFf, Dd, Dd, true, false);
        add_ln_kernel<<<TOK, 256>>>(y, tmp);
    }

    // ---------------- Output projection + vocab softmax ----------------
    gemm128(y, out_w, out_b, out, TOK, Vv, Dd, Dd, Vv, Vv, true, false);
    softmax_rows<<<TOK, 256>>>(out, Vv, 0);
}

// round 3
// speedup vs baseline: 2.0945x; 1.1758x over previous
#include <cuda_runtime.h>
#include <cuda_bf16.h>
#include <math.h>
#include <stdint.h>

#define Bn   4
#define Ss   512
#define Dd   512
#define Hh   8
#define DKk  64
#define Nl   6
#define Vv   32000
#define FFf  2048
#define TOK  (Bn*Ss)

// ---------------- fp32 scratch ----------------
__device__ __align__(16) float g_x[TOK*Dd];
__device__ __align__(16) float g_y[TOK*Dd];
__device__ __align__(16) float g_q[TOK*Dd];
__device__ __align__(16) float g_kv[2*TOK*Dd];
__device__ __align__(16) float g_attn[TOK*Dd];
__device__ __align__(16) float g_tmp[TOK*Dd];
__device__ __align__(16) float g_ffn[TOK*FFf];
__device__ __align__(16) float g_scores[(size_t)Bn*Hh*Ss*Ss];

// ---------------- packed bf16x2 hi/lo converted operands ----------------
#define DD2  (Dd*Dd/2)
__device__ __align__(16) uint32_t g_encW_h[24*DD2], g_encW_l[24*DD2];
__device__ __align__(16) uint32_t g_decSW_h[24*DD2], g_decSW_l[24*DD2];
__device__ __align__(16) uint32_t g_decCW_h[24*DD2], g_decCW_l[24*DD2];
#define W1SZ (Dd*FFf/2)
__device__ __align__(16) uint32_t g_encW1_h[Nl*W1SZ], g_encW1_l[Nl*W1SZ];
__device__ __align__(16) uint32_t g_encW2_h[Nl*W1SZ], g_encW2_l[Nl*W1SZ];
__device__ __align__(16) uint32_t g_decW1_h[Nl*W1SZ], g_decW1_l[Nl*W1SZ];
__device__ __align__(16) uint32_t g_decW2_h[Nl*W1SZ], g_decW2_l[Nl*W1SZ];
#define OWSZ (Dd*Vv/2)
__device__ __align__(16) uint32_t g_outW_h[OWSZ], g_outW_l[OWSZ];
#define KVC  (TOK*Dd/2)
__device__ __align__(16) uint32_t g_Kc_h[KVC], g_Kc_l[KVC];
__device__ __align__(16) uint32_t g_Vc_h[KVC], g_Vc_l[KVC];

// ---------------- helpers ----------------
__device__ __forceinline__ void cvt_pair(float x0, float x1, uint32_t& hi, uint32_t& lo)
{
    uint32_t h;
    asm("cvt.rn.bf16x2.f32 %0, %1, %2;" : "=r"(h) : "f"(x1), "f"(x0));
    __nv_bfloat162 hb = *reinterpret_cast<__nv_bfloat162*>(&h);
    float r0 = x0 - __bfloat162float(hb.x);
    float r1 = x1 - __bfloat162float(hb.y);
    uint32_t l;
    asm("cvt.rn.bf16x2.f32 %0, %1, %2;" : "=r"(l) : "f"(r1), "f"(r0));
    hi = h; lo = l;
}

__device__ __forceinline__ void mma16816(float* c, const uint32_t* a, const uint32_t* b)
{
    asm volatile(
        "mma.sync.aligned.m16n8k16.row.col.f32.bf16.bf16.f32 "
        "{%0,%1,%2,%3}, {%4,%5,%6,%7}, {%8,%9}, {%0,%1,%2,%3};\n"
        : "+f"(c[0]), "+f"(c[1]), "+f"(c[2]), "+f"(c[3])
        : "r"(a[0]), "r"(a[1]), "r"(a[2]), "r"(a[3]), "r"(b[0]), "r"(b[1]));
}

__device__ __forceinline__ void cp_async16(uint32_t s, const void* g)
{
    asm volatile("cp.async.cg.shared.global [%0], [%1], 16;" :: "r"(s), "l"(g));
}
#define CP_COMMIT() asm volatile("cp.async.commit_group;")
#define CP_WAIT0()  asm volatile("cp.async.wait_group 0;")

// ---------------- conversion kernels ----------------
__global__ __launch_bounds__(256)
void convB(const float* __restrict__ W, uint32_t* __restrict__ H,
           uint32_t* __restrict__ L, int C)
{
    long long kp = blockIdx.y;
    int c = blockIdx.x * 256 + threadIdx.x;
    float a = W[(2*kp) * (long long)C + c];
    float b = W[(2*kp+1) * (long long)C + c];
    uint32_t h, l; cvt_pair(a, b, h, l);
    long long o = kp * C + c;
    H[o] = h; L[o] = l;
}

__global__ __launch_bounds__(256)
void convAT(const float* __restrict__ X, uint32_t* __restrict__ H,
            uint32_t* __restrict__ L, int Mdim, int Kdim)
{
    __shared__ float s[32][33];
    int m0 = blockIdx.x * 32, k0 = blockIdx.y * 32;
    int tx = threadIdx.x & 31, ty = threadIdx.x >> 5;
#pragma unroll
    for (int i = 0; i < 4; i++) {
        int m = ty + i * 8;
        s[m][tx] = X[(long long)(m0 + m) * Kdim + k0 + tx];
    }
    __syncthreads();
    int om = threadIdx.x & 31, okp = threadIdx.x >> 5;
#pragma unroll
    for (int i = 0; i < 2; i++) {
        int kp = okp + i * 8;
        uint32_t h, l;
        cvt_pair(s[om][2*kp], s[om][2*kp+1], h, l);
        long long o = (long long)(k0/2 + kp) * Mdim + m0 + om;
        H[o] = h; L[o] = l;
    }
}

// ---------------- GEMM ----------------
template<int TBM, int TBN, int NTHREADS, int WARPS_M>
__global__ __launch_bounds__(NTHREADS)
void gemm_pk(const float* __restrict__ A,
             const uint32_t* __restrict__ BH, const uint32_t* __restrict__ BL,
             const float* __restrict__ bias, float* __restrict__ C,
             int K, int lda, int ldbp, int ldc,
             long long sAo, long long sAi, long long sBo, long long sBi,
             long long sCo, long long sCi, int Hsub,
             float alpha, int doBias, int doRelu)
{
    constexpr int WARPS   = NTHREADS / 32;
    constexpr int WARPS_N = WARPS / WARPS_M;
    constexpr int WM = TBM / WARPS_M;
    constexpr int WN = TBN / WARPS_N;
    constexpr int MT = WM / 16;
    constexpr int NT = WN / 8;
    constexpr int AS = TBM + 8;
    constexpr int BS = TBN + 8;
    constexpr int ASZ = 16 * AS;
    constexpr int BSZ = 16 * BS;
    constexpr int PF = TBM * 32 / (4 * NTHREADS);
    constexpr int BC = (16 * (TBN / 4)) / NTHREADS;

    extern __shared__ uint32_t smem[];
    uint32_t* sAh = smem;
    uint32_t* sAl = smem + 2 * ASZ;
    uint32_t* sBh = smem + 4 * ASZ;
    uint32_t* sBl = smem + 4 * ASZ + 2 * BSZ;

    int z = blockIdx.z;
    int zo = z / Hsub, zi = z % Hsub;
    const float*    Ab  = A  + zo * sAo + zi * sAi;
    const uint32_t* Bhb = BH + zo * sBo + zi * sBi;
    const uint32_t* Blb = BL + zo * sBo + zi * sBi;
    float*          Cb  = C  + zo * sCo + zi * sCi;

    int tid = threadIdx.x;
    int wid = tid >> 5, lane = tid & 31;
    int wm = wid % WARPS_M, wn = wid / WARPS_M;
    int group = lane >> 2, tig = lane & 3;
    int row0 = blockIdx.x * TBM;
    int col0 = blockIdx.y * TBN;

    float4 pf[PF];

    auto loadA = [&](int k0) {
#pragma unroll
        for (int i = 0; i < PF; i++) {
            int idx = tid + i * NTHREADS;
            int r = idx >> 3, c4 = idx & 7;
            pf[i] = *reinterpret_cast<const float4*>(
                Ab + (long long)(row0 + r) * lda + k0 + c4 * 4);
        }
    };
    auto cvtStoreA = [&](int st) {
        uint32_t* ah = sAh + st * ASZ;
        uint32_t* al = sAl + st * ASZ;
#pragma unroll
        for (int i = 0; i < PF; i++) {
            int idx = tid + i * NTHREADS;
            int r = idx >> 3, c4 = idx & 7;
            uint32_t h0, l0, h1, l1;
            cvt_pair(pf[i].x, pf[i].y, h0, l0);
            cvt_pair(pf[i].z, pf[i].w, h1, l1);
            ah[(c4*2    ) * AS + r] = h0;  al[(c4*2    ) * AS + r] = l0;
            ah[(c4*2 + 1) * AS + r] = h1;  al[(c4*2 + 1) * AS + r] = l1;
        }
    };
    auto cpB = [&](int k0, int st) {
        int kp0 = k0 >> 1;
        uint32_t bh0 = (uint32_t)__cvta_generic_to_shared(sBh + st * BSZ);
        uint32_t bl0 = (uint32_t)__cvta_generic_to_shared(sBl + st * BSZ);
#pragma unroll
        for (int j = 0; j < BC; j++) {
            int ci = tid + j * NTHREADS;
            int rr = ci / (TBN / 4), cc = ci % (TBN / 4);
            long long go = (long long)(kp0 + rr) * ldbp + col0 + cc * 4;
            uint32_t so = (rr * BS + cc * 4) * 4;
            cp_async16(bh0 + so, Bhb + go);
            cp_async16(bl0 + so, Blb + go);
        }
    };

    float acc[MT][NT][4];
#pragma unroll
    for (int i = 0; i < MT; i++)
#pragma unroll
        for (int j = 0; j < NT; j++)
#pragma unroll
            for (int t = 0; t < 4; t++) acc[i][j][t] = 0.f;

    loadA(0);
    cpB(0, 0); CP_COMMIT();
    cvtStoreA(0);
    CP_WAIT0();
    __syncthreads();

    int st = 0;
    for (int k0 = 0; k0 < K; k0 += 32) {
        bool has_next = (k0 + 32) < K;
        if (has_next) {
            loadA(k0 + 32);
            cpB(k0 + 32, st ^ 1); CP_COMMIT();
        }
        const uint32_t* Ahs = sAh + st * ASZ;
        const uint32_t* Als = sAl + st * ASZ;
        const uint32_t* Bhs = sBh + st * BSZ;
        const uint32_t* Bls = sBl + st * BSZ;
#pragma unroll
        for (int ks = 0; ks < 2; ks++) {
            uint32_t ah[MT][4], al[MT][4], bh[NT][2], bl[NT][2];
            int kp0 = ks * 8 + tig, kp1 = kp0 + 4;
#pragma unroll
            for (int mt = 0; mt < MT; mt++) {
                int r = wm * WM + mt * 16 + group;
                ah[mt][0] = Ahs[kp0 * AS + r];     al[mt][0] = Als[kp0 * AS + r];
                ah[mt][1] = Ahs[kp0 * AS + r + 8]; al[mt][1] = Als[kp0 * AS + r + 8];
                ah[mt][2] = Ahs[kp1 * AS + r];     al[mt][2] = Als[kp1 * AS + r];
                ah[mt][3] = Ahs[kp1 * AS + r + 8]; al[mt][3] = Als[kp1 * AS + r + 8];
            }
#pragma unroll
            for (int nt = 0; nt < NT; nt++) {
                int c = wn * WN + nt * 8 + group;
                bh[nt][0] = Bhs[kp0 * BS + c];  bl[nt][0] = Bls[kp0 * BS + c];
                bh[nt][1] = Bhs[kp1 * BS + c];  bl[nt][1] = Bls[kp1 * BS + c];
            }
#pragma unroll
            for (int mt = 0; mt < MT; mt++)
#pragma unroll
                for (int nt = 0; nt < NT; nt++) {
                    mma16816(acc[mt][nt], ah[mt], bh[nt]);
                    mma16816(acc[mt][nt], al[mt], bh[nt]);
                    mma16816(acc[mt][nt], ah[mt], bl[nt]);
                }
        }
        if (has_next) {
            cvtStoreA(st ^ 1);
            CP_WAIT0();
        }
        __syncthreads();
        st ^= 1;
    }

#pragma unroll
    for (int mt = 0; mt < MT; mt++) {
        int r = row0 + wm * WM + mt * 16 + group;
#pragma unroll
        for (int nt = 0; nt < NT; nt++) {
            int c = col0 + wn * WN + nt * 8 + tig * 2;
            float v00 = acc[mt][nt][0] * alpha;
            float v01 = acc[mt][nt][1] * alpha;
            float v10 = acc[mt][nt][2] * alpha;
            float v11 = acc[mt][nt][3] * alpha;
            if (doBias) {
                float2 bb = *reinterpret_cast<const float2*>(&bias[c]);
                v00 += bb.x; v01 += bb.y; v10 += bb.x; v11 += bb.y;
            }
            if (doRelu) {
                v00 = fmaxf(v00, 0.f); v01 = fmaxf(v01, 0.f);
                v10 = fmaxf(v10, 0.f); v11 = fmaxf(v11, 0.f);
            }
            *reinterpret_cast<float2*>(&Cb[(long long)r * ldc + c])       = make_float2(v00, v01);
            *reinterpret_cast<float2*>(&Cb[(long long)(r + 8) * ldc + c]) = make_float2(v10, v11);
        }
    }
}

// ---------------- scores softmax (L=512) ----------
__global__ __launch_bounds__(256)
void softmax_rows(float* __restrict__ P, int causal)
{
    long long row = blockIdx.x;
    float* p = P + row * (long long)Ss;
    int qpos = (int)(row % Ss);
    int t = threadIdx.x;
    __shared__ float red[256];

    float v0 = p[t], v1 = p[t + 256];
    if (causal) {
        if (t > qpos) v0 = -1e9f;
        if (t + 256 > qpos) v1 = -1e9f;
    }
    float mx = fmaxf(v0, v1);
    red[t] = mx; __syncthreads();
    for (int o = 128; o; o >>= 1) { if (t < o) red[t] = fmaxf(red[t], red[t + o]); __syncthreads(); }
    mx = red[0]; __syncthreads();
    float e0 = __expf(v0 - mx), e1 = __expf(v1 - mx);
    red[t] = e0 + e1; __syncthreads();
    for (int o = 128; o; o >>= 1) { if (t < o) red[t] += red[t + o]; __syncthreads(); }
    float inv = 1.0f / red[0];
    p[t] = e0 * inv;
    p[t + 256] = e1 * inv;
}

// ---------------- vocab softmax ----------
__global__ __launch_bounds__(1024)
void softmax_vocab(float* __restrict__ P)
{
    float* p = P + (long long)blockIdx.x * Vv;
    int t = threadIdx.x;
    __shared__ float red[32];
    float v[32];
    float mx = -3.0e38f;
#pragma unroll
    for (int i = 0; i < 32; i++) {
        int idx = t + i * 1024;
        v[i] = (idx < Vv) ? p[idx] : -3.0e38f;
        mx = fmaxf(mx, v[i]);
    }
    for (int o = 16; o; o >>= 1) mx = fmaxf(mx, __shfl_xor_sync(0xffffffffu, mx, o));
    if ((t & 31) == 0) red[t >> 5] = mx;
    __syncthreads();
    if (t < 32) {
        float m2 = red[t];
        for (int o = 16; o; o >>= 1) m2 = fmaxf(m2, __shfl_xor_sync(0xffffffffu, m2, o));
        if (t == 0) red[0] = m2;
    }
    __syncthreads();
    mx = red[0];
    __syncthreads();
    float sum = 0.f;
#pragma unroll
    for (int i = 0; i < 32; i++) { v[i] = __expf(v[i] - mx); sum += v[i]; }
    for (int o = 16; o; o >>= 1) sum += __shfl_xor_sync(0xffffffffu, sum, o);
    if ((t & 31) == 0) red[t >> 5] = sum;
    __syncthreads();
    if (t < 32) {
        float s2 = red[t];
        for (int o = 16; o; o >>= 1) s2 += __shfl_xor_sync(0xffffffffu, s2, o);
        if (t == 0) red[0] = s2;
    }
    __syncthreads();
    float inv = 1.0f / red[0];
#pragma unroll
    for (int i = 0; i < 32; i++) {
        int idx = t + i * 1024;
        if (idx < Vv) p[idx] = v[i] * inv;
    }
}

// ---------------- add + LayerNorm ----------
__global__ __launch_bounds__(256)
void add_ln_kernel(float* __restrict__ x, const float* __restrict__ sub)
{
    int row = blockIdx.x;
    float* xr = x + (long long)row * Dd;
    const float* sr = sub + (long long)row * Dd;
    int t = threadIdx.x;
    __shared__ float red[256];

    float v0 = xr[t] + sr[t];
    float v1 = xr[t + 256] + sr[t + 256];
    red[t] = v0 + v1; __syncthreads();
    for (int o = 128; o; o >>= 1) { if (t < o) red[t] += red[t + o]; __syncthreads(); }
    float mu = red[0] * (1.0f / 512.0f); __syncthreads();
    float d0 = v0 - mu, d1 = v1 - mu;
    red[t] = d0 * d0 + d1 * d1; __syncthreads();
    for (int o = 128; o; o >>= 1) { if (t < o) red[t] += red[t + o]; __syncthreads(); }
    float inv = rsqrtf(red[0] * (1.0f / 512.0f) + 1e-5f);
    xr[t] = d0 * inv;
    xr[t + 256] = d1 * inv;
}

// ---------------- embedding + PE ----------
__global__ __launch_bounds__(512)
void embed_pe_kernel(const int* __restrict__ tok, const float* __restrict__ emb,
                     float* __restrict__ out)
{
    int idx = blockIdx.x;
    int s = idx % Ss;
    int j = threadIdx.x;
    int tk = tok[idx];
    float ang = (float)s * powf(10000.0f, -2.0f * (float)j / 512.0f);
    float pe = (j & 1) ? cosf(ang) : sinf(ang);
    out[(long long)idx * Dd + j] = emb[(long long)tk * Dd + j] + pe;
}

// ---------------- host ----------------
static const int SMEM64  = (4 * 2 * 16 * (64 + 8)) * 4;
static const int SMEM128 = (4 * 2 * 16 * (128 + 8)) * 4;

static void gemm64(const float* A, const uint32_t* BH, const uint32_t* BL,
                   const float* bias, float* C,
                   int M, int N, int K, int lda, int ldbp, int ldc,
                   bool doBias, bool doRelu)
{
    dim3 g(M / 64, N / 64, 1);
    gemm_pk<64, 64, 128, 2><<<g, 128, SMEM64>>>(A, BH, BL, bias, C, K, lda, ldbp, ldc,
        0, 0, 0, 0, 0, 0, 1, 1.0f, doBias ? 1 : 0, doRelu ? 1 : 0);
}

static void gemm128(const float* A, const uint32_t* BH, const uint32_t* BL,
                    const float* bias, float* C,
                    int M, int N, int K, int lda, int ldbp, int ldc,
                    bool doBias, bool doRelu)
{
    dim3 g(M / 128, N / 128, 1);
    gemm_pk<128, 128, 256, 4><<<g, 256, SMEM128>>>(A, BH, BL, bias, C, K, lda, ldbp, ldc,
        0, 0, 0, 0, 0, 0, 1, 1.0f, doBias ? 1 : 0, doRelu ? 1 : 0);
}

static void run_mha(const float* xq, const float* xkv,
                    const uint32_t* wh, const uint32_t* wl,
                    float* out, bool causal,
                    float* q, float* kv, float* attn, float* scores,
                    uint32_t* Kch, uint32_t* Kcl, uint32_t* Vch, uint32_t* Vcl)
{
    gemm64(xq, wh, wl, nullptr, q, TOK, Dd, Dd, Dd, Dd, Dd, false, false);
    {
        dim3 g(TOK / 64, Dd / 64, 2);
        gemm_pk<64, 64, 128, 2><<<g, 128, SMEM64>>>(xkv, wh + DD2, wl + DD2, nullptr, kv,
            Dd, Dd, Dd, Dd,
            0, 0, 0, DD2, 0, (long long)TOK * Dd, 2,
            1.0f, 0, 0);
    }
    const float* k = kv;
    const float* v = kv + (long long)TOK * Dd;

    convAT<<<dim3(TOK / 32, Dd / 32), 256>>>(k, Kch, Kcl, TOK, Dd);
    convB<<<dim3(Dd / 256, TOK / 2), 256>>>(v, Vch, Vcl, Dd);

    {
        dim3 g(Ss / 64, Ss / 64, Bn * Hh);
        gemm_pk<64, 64, 128, 2><<<g, 128, SMEM64>>>(q, Kch, Kcl, nullptr, scores,
            DKk, Dd, TOK, Ss,
            (long long)Ss * Dd, DKk,
            Ss, (long long)(DKk / 2) * TOK,
            (long long)Hh * Ss * Ss, (long long)Ss * Ss,
            Hh, 0.125f, 0, 0);
    }
    softmax_rows<<<Bn * Hh * Ss, 256>>>(scores, causal ? 1 : 0);

    {
        dim3 g(Ss / 64, DKk / 64, Bn * Hh);
        gemm_pk<64, 64, 128, 2><<<g, 128, SMEM64>>>(scores, Vch, Vcl, nullptr, attn,
            Ss, Ss, Dd, Dd,
            (long long)Hh * Ss * Ss, (long long)Ss * Ss,
            (long long)(Ss / 2) * Dd, DKk,
            (long long)Ss * Dd, DKk,
            Hh, 1.0f, 0, 0);
    }
    gemm64(attn, wh + 3 * DD2, wl + 3 * DD2, nullptr, out, TOK, Dd, Dd, Dd, Dd, Dd, false, false);
}

extern "C" void kernel_launch(void* const* d_in, const int* in_sizes, int n_in,
                              void* d_out, int out_size)
{
    const int*   src           = (const int*)  d_in[0];
    const int*   trg           = (const int*)  d_in[1];
    const float* src_emb       = (const float*)d_in[2];
    const float* trg_emb       = (const float*)d_in[3];
    const float* enc_qkvo      = (const float*)d_in[4];
    const float* enc_ffn_w1    = (const float*)d_in[5];
    const float* enc_ffn_b1    = (const float*)d_in[6];
    const float* enc_ffn_w2    = (const float*)d_in[7];
    const float* enc_ffn_b2    = (const float*)d_in[8];
    const float* dec_self_qkvo = (const float*)d_in[9];
    const float* dec_cross_qkvo= (const float*)d_in[10];
    const float* dec_ffn_w1    = (const float*)d_in[11];
    const float* dec_ffn_b1    = (const float*)d_in[12];
    const float* dec_ffn_w2    = (const float*)d_in[13];
    const float* dec_ffn_b2    = (const float*)d_in[14];
    const float* out_w         = (const float*)d_in[15];
    const float* out_b         = (const float*)d_in[16];
    float* out = (float*)d_out;

    cudaFuncSetAttribute(gemm_pk<128, 128, 256, 4>,
                         cudaFuncAttributeMaxDynamicSharedMemorySize, SMEM128);

    float *x, *y, *q, *kv, *attn, *tmp, *ffn, *scores;
    uint32_t *encWh, *encWl, *decSWh, *decSWl, *decCWh, *decCWl;
    uint32_t *eW1h, *eW1l, *eW2h, *eW2l, *dW1h, *dW1l, *dW2h, *dW2l;
    uint32_t *oWh, *oWl, *Kch, *Kcl, *Vch, *Vcl;
    cudaGetSymbolAddress((void**)&x,      g_x);
    cudaGetSymbolAddress((void**)&y,      g_y);
    cudaGetSymbolAddress((void**)&q,      g_q);
    cudaGetSymbolAddress((void**)&kv,     g_kv);
    cudaGetSymbolAddress((void**)&attn,   g_attn);
    cudaGetSymbolAddress((void**)&tmp,    g_tmp);
    cudaGetSymbolAddress((void**)&ffn,    g_ffn);
    cudaGetSymbolAddress((void**)&scores, g_scores);
    cudaGetSymbolAddress((void**)&encWh,  g_encW_h);  cudaGetSymbolAddress((void**)&encWl, g_encW_l);
    cudaGetSymbolAddress((void**)&decSWh, g_decSW_h); cudaGetSymbolAddress((void**)&decSWl, g_decSW_l);
    cudaGetSymbolAddress((void**)&decCWh, g_decCW_h); cudaGetSymbolAddress((void**)&decCWl, g_decCW_l);
    cudaGetSymbolAddress((void**)&eW1h,   g_encW1_h); cudaGetSymbolAddress((void**)&eW1l, g_encW1_l);
    cudaGetSymbolAddress((void**)&eW2h,   g_encW2_h); cudaGetSymbolAddress((void**)&eW2l, g_encW2_l);
    cudaGetSymbolAddress((void**)&dW1h,   g_decW1_h); cudaGetSymbolAddress((void**)&dW1l, g_decW1_l);
    cudaGetSymbolAddress((void**)&dW2h,   g_decW2_h); cudaGetSymbolAddress((void**)&dW2l, g_decW2_l);
    cudaGetSymbolAddress((void**)&oWh,    g_outW_h);  cudaGetSymbolAddress((void**)&oWl, g_outW_l);
    cudaGetSymbolAddress((void**)&Kch,    g_Kc_h);    cudaGetSymbolAddress((void**)&Kcl, g_Kc_l);
    cudaGetSymbolAddress((void**)&Vch,    g_Vc_h);    cudaGetSymbolAddress((void**)&Vcl, g_Vc_l);

    convB<<<dim3(Dd / 256,  24 * Dd / 2), 256>>>(enc_qkvo,       encWh, encWl, Dd);
    convB<<<dim3(Dd / 256,  24 * Dd / 2), 256>>>(dec_self_qkvo,  decSWh, decSWl, Dd);
    convB<<<dim3(Dd / 256,  24 * Dd / 2), 256>>>(dec_cross_qkvo, decCWh, decCWl, Dd);
    convB<<<dim3(FFf / 256, Nl * Dd / 2), 256>>>(enc_ffn_w1, eW1h, eW1l, FFf);
    convB<<<dim3(Dd / 256,  Nl * FFf / 2), 256>>>(enc_ffn_w2, eW2h, eW2l, Dd);
    convB<<<dim3(FFf / 256, Nl * Dd / 2), 256>>>(dec_ffn_w1, dW1h, dW1l, FFf);
    convB<<<dim3(Dd / 256,  Nl * FFf / 2), 256>>>(dec_ffn_w2, dW2h, dW2l, Dd);
    convB<<<dim3(Vv / 256,  Dd / 2), 256>>>(out_w, oWh, oWl, Vv);

    embed_pe_kernel<<<TOK, 512>>>(src, src_emb, x);
    embed_pe_kernel<<<TOK, 512>>>(trg, trg_emb, y);

    for (int i = 0; i < Nl; i++) {
        run_mha(x, x, encWh + (long long)i * 4 * DD2, encWl + (long long)i * 4 * DD2,
                tmp, false, q, kv, attn, scores, Kch, Kcl, Vch, Vcl);
        add_ln_kernel<<<TOK, 256>>>(x, tmp);

        gemm128(x, eW1h + (long long)i * W1SZ, eW1l + (long long)i * W1SZ,
                enc_ffn_b1 + (long long)i * FFf, ffn,
                TOK, FFf, Dd, Dd, FFf, FFf, true, true);
        gemm64(ffn, eW2h + (long long)i * W1SZ, eW2l + (long long)i * W1SZ,
               enc_ffn_b2 + (long long)i * Dd, tmp,
               TOK, Dd, FFf, FFf, Dd, Dd, true, false);
        add_ln_kernel<<<TOK, 256>>>(x, tmp);
    }

    for (int i = 0; i < Nl; i++) {
        run_mha(y, y, decSWh + (long long)i * 4 * DD2, decSWl + (long long)i * 4 * DD2,
                tmp, true, q, kv, attn, scores, Kch, Kcl, Vch, Vcl);
        add_ln_kernel<<<TOK, 256>>>(y, tmp);

        run_mha(y, x, decCWh + (long long)i * 4 * DD2, decCWl + (long long)i * 4 * DD2,
                tmp, false, q, kv, attn, scores, Kch, Kcl, Vch, Vcl);
        add_ln_kernel<<<TOK, 256>>>(y, tmp);

        gemm128(y, dW1h + (long long)i * W1SZ, dW1l + (long long)i * W1SZ,
                dec_ffn_b1 + (long long)i * FFf, ffn,
                TOK, FFf, Dd, Dd, FFf, FFf, true, true);
        gemm64(ffn, dW2h + (long long)i * W1SZ, dW2l + (long long)i * W1SZ,
               dec_ffn_b2 + (long long)i * Dd, tmp,
               TOK, Dd, FFf, FFf, Dd, Dd, true, false);
        add_ln_kernel<<<TOK, 256>>>(y, tmp);
    }

    gemm128(y, oWh, oWl, out_b, out, TOK, Vv, Dd, Dd, Vv, Vv, true, false);
    softmax_vocab<<<TOK, 1024>>>(out);
}

// round 4
// speedup vs baseline: 2.3872x; 1.1397x over previous
#include <cuda_runtime.h>
#include <cuda_bf16.h>
#include <math.h>
#include <stdint.h>

#define Bn   4
#define Ss   512
#define Dd   512
#define Hh   8
#define DKk  64
#define Nl   6
#define Vv   32000
#define FFf  2048
#define TOK  (Bn*Ss)

// ---------------- fp32 scratch ----------------
__device__ __align__(16) float g_x[TOK*Dd];
__device__ __align__(16) float g_y[TOK*Dd];
__device__ __align__(16) float g_qkv[3*TOK*Dd];
__device__ __align__(16) float g_attn[TOK*Dd];
__device__ __align__(16) float g_tmp[TOK*Dd];
__device__ __align__(16) float g_ffn[TOK*FFf];
__device__ __align__(16) float g_scores[(size_t)Bn*Hh*Ss*Ss];

// ---------------- packed bf16x2 hi/lo operands ----------------
#define DD2  (Dd*Dd/2)
__device__ __align__(16) uint32_t g_encW_h[24*DD2], g_encW_l[24*DD2];
__device__ __align__(16) uint32_t g_decSW_h[24*DD2], g_decSW_l[24*DD2];
__device__ __align__(16) uint32_t g_decCW_h[24*DD2], g_decCW_l[24*DD2];
#define W1SZ (Dd*FFf/2)
__device__ __align__(16) uint32_t g_encW1_h[Nl*W1SZ], g_encW1_l[Nl*W1SZ];
__device__ __align__(16) uint32_t g_encW2_h[Nl*W1SZ], g_encW2_l[Nl*W1SZ];
__device__ __align__(16) uint32_t g_decW1_h[Nl*W1SZ], g_decW1_l[Nl*W1SZ];
__device__ __align__(16) uint32_t g_decW2_h[Nl*W1SZ], g_decW2_l[Nl*W1SZ];
#define OWSZ (Dd*Vv/2)
__device__ __align__(16) uint32_t g_outW_h[OWSZ], g_outW_l[OWSZ];
#define KVC  (TOK*Dd/2)
__device__ __align__(16) uint32_t g_Kc_h[KVC], g_Kc_l[KVC];
__device__ __align__(16) uint32_t g_Vc_h[KVC], g_Vc_l[KVC];
// packed-transposed activation buffer (max FFf/2 x TOK)
#define ATSZ ((FFf/2)*TOK)
__device__ __align__(16) uint32_t g_aT_h[ATSZ], g_aT_l[ATSZ];
// encoder-output packed (for all cross-attn layers)
__device__ __align__(16) uint32_t g_xeT_h[KVC], g_xeT_l[KVC];

// ---------------- helpers ----------------
__device__ __forceinline__ void cvt_pair(float x0, float x1, uint32_t& hi, uint32_t& lo)
{
    uint32_t h;
    asm("cvt.rn.bf16x2.f32 %0, %1, %2;" : "=r"(h) : "f"(x1), "f"(x0));
    __nv_bfloat162 hb = *reinterpret_cast<__nv_bfloat162*>(&h);
    float r0 = x0 - __bfloat162float(hb.x);
    float r1 = x1 - __bfloat162float(hb.y);
    uint32_t l;
    asm("cvt.rn.bf16x2.f32 %0, %1, %2;" : "=r"(l) : "f"(r1), "f"(r0));
    hi = h; lo = l;
}

__device__ __forceinline__ void mma16816(float* c, const uint32_t* a, const uint32_t* b)
{
    asm volatile(
        "mma.sync.aligned.m16n8k16.row.col.f32.bf16.bf16.f32 "
        "{%0,%1,%2,%3}, {%4,%5,%6,%7}, {%8,%9}, {%0,%1,%2,%3};\n"
        : "+f"(c[0]), "+f"(c[1]), "+f"(c[2]), "+f"(c[3])
        : "r"(a[0]), "r"(a[1]), "r"(a[2]), "r"(a[3]), "r"(b[0]), "r"(b[1]));
}

__device__ __forceinline__ void cp_async16(uint32_t s, const void* g)
{
    asm volatile("cp.async.cg.shared.global [%0], [%1], 16;" :: "r"(s), "l"(g));
}
#define CP_COMMIT() asm volatile("cp.async.commit_group;")
#define CP_WAIT0()  asm volatile("cp.async.wait_group 0;")

// ---------------- conversion kernels ----------------
__global__ __launch_bounds__(256)
void convB(const float* __restrict__ W, uint32_t* __restrict__ H,
           uint32_t* __restrict__ L, int C)
{
    long long kp = blockIdx.y;
    int c = blockIdx.x * 256 + threadIdx.x;
    float a = W[(2*kp) * (long long)C + c];
    float b = W[(2*kp+1) * (long long)C + c];
    uint32_t h, l; cvt_pair(a, b, h, l);
    long long o = kp * C + c;
    H[o] = h; L[o] = l;
}

// transpose-convert: X [M][K] fp32 -> H/L [K/2][M]
__global__ __launch_bounds__(256)
void convAT(const float* __restrict__ X, uint32_t* __restrict__ H,
            uint32_t* __restrict__ L, int Mdim, int Kdim)
{
    __shared__ float s[32][33];
    int m0 = blockIdx.x * 32, k0 = blockIdx.y * 32;
    int tx = threadIdx.x & 31, ty = threadIdx.x >> 5;
#pragma unroll
    for (int i = 0; i < 4; i++) {
        int m = ty + i * 8;
        s[m][tx] = X[(long long)(m0 + m) * Kdim + k0 + tx];
    }
    __syncthreads();
    int om = threadIdx.x & 31, okp = threadIdx.x >> 5;
#pragma unroll
    for (int i = 0; i < 2; i++) {
        int kp = okp + i * 8;
        uint32_t h, l;
        cvt_pair(s[om][2*kp], s[om][2*kp+1], h, l);
        long long o = (long long)(k0/2 + kp) * Mdim + m0 + om;
        H[o] = h; L[o] = l;
    }
}

// ---------------- all-packed GEMM (A and B pre-packed hi/lo) ----------------
template<int TBM, int TBN, int NTHREADS, int WARPS_M, int STAGES>
__global__ __launch_bounds__(NTHREADS)
void gemm_ap(const uint32_t* __restrict__ AH, const uint32_t* __restrict__ AL,
             const uint32_t* __restrict__ BH, const uint32_t* __restrict__ BL,
             const float* __restrict__ bias, float* __restrict__ C,
             int K, int ldap, int ldbp, int ldc,
             long long sAo, long long sAi, long long sBo, long long sBi,
             long long sCo, long long sCi, int Hsub,
             float alpha, int doBias, int doRelu)
{
    constexpr int WARPS   = NTHREADS / 32;
    constexpr int WARPS_N = WARPS / WARPS_M;
    constexpr int WM = TBM / WARPS_M;
    constexpr int WN = TBN / WARPS_N;
    constexpr int MT = WM / 16;
    constexpr int NT = WN / 8;
    constexpr int AS = TBM + 8;
    constexpr int BS = TBN + 8;
    constexpr int ASZ = 16 * AS;
    constexpr int BSZ = 16 * BS;
    constexpr int AC = (16 * (TBM / 4)) / NTHREADS;
    constexpr int BC = (16 * (TBN / 4)) / NTHREADS;

    extern __shared__ uint32_t smem[];
    uint32_t* sAh = smem;
    uint32_t* sAl = smem + STAGES * ASZ;
    uint32_t* sBh = smem + 2 * STAGES * ASZ;
    uint32_t* sBl = smem + 2 * STAGES * ASZ + STAGES * BSZ;

    int z = blockIdx.z;
    int zo = z / Hsub, zi = z % Hsub;
    const uint32_t* Ahb = AH + zo * sAo + zi * sAi;
    const uint32_t* Alb = AL + zo * sAo + zi * sAi;
    const uint32_t* Bhb = BH + zo * sBo + zi * sBi;
    const uint32_t* Blb = BL + zo * sBo + zi * sBi;
    float*          Cb  = C  + zo * sCo + zi * sCi;

    int tid = threadIdx.x;
    int wid = tid >> 5, lane = tid & 31;
    int wm = wid % WARPS_M, wn = wid / WARPS_M;
    int group = lane >> 2, tig = lane & 3;
    int row0 = blockIdx.x * TBM;
    int col0 = blockIdx.y * TBN;

    auto cpStage = [&](int k0, int st) {
        int kp0 = k0 >> 1;
        uint32_t ah0 = (uint32_t)__cvta_generic_to_shared(sAh + st * ASZ);
        uint32_t al0 = (uint32_t)__cvta_generic_to_shared(sAl + st * ASZ);
#pragma unroll
        for (int j = 0; j < AC; j++) {
            int ci = tid + j * NTHREADS;
            int rr = ci / (TBM / 4), cc = ci % (TBM / 4);
            long long go = (long long)(kp0 + rr) * ldap + row0 + cc * 4;
            uint32_t so = (rr * AS + cc * 4) * 4;
            cp_async16(ah0 + so, Ahb + go);
            cp_async16(al0 + so, Alb + go);
        }
        uint32_t bh0 = (uint32_t)__cvta_generic_to_shared(sBh + st * BSZ);
        uint32_t bl0 = (uint32_t)__cvta_generic_to_shared(sBl + st * BSZ);
#pragma unroll
        for (int j = 0; j < BC; j++) {
            int ci = tid + j * NTHREADS;
            int rr = ci / (TBN / 4), cc = ci % (TBN / 4);
            long long go = (long long)(kp0 + rr) * ldbp + col0 + cc * 4;
            uint32_t so = (rr * BS + cc * 4) * 4;
            cp_async16(bh0 + so, Bhb + go);
            cp_async16(bl0 + so, Blb + go);
        }
        CP_COMMIT();
    };

    float acc[MT][NT][4];
#pragma unroll
    for (int i = 0; i < MT; i++)
#pragma unroll
        for (int j = 0; j < NT; j++)
#pragma unroll
            for (int t = 0; t < 4; t++) acc[i][j][t] = 0.f;

    int kpref = 0;
#pragma unroll
    for (int s = 0; s < STAGES - 1; s++) { cpStage(kpref, s); kpref += 32; }
    asm volatile("cp.async.wait_group %0;" :: "n"(STAGES - 2));
    __syncthreads();

    int st = 0;
    for (int k0 = 0; k0 < K; k0 += 32) {
        const uint32_t* Ahs = sAh + st * ASZ;
        const uint32_t* Als = sAl + st * ASZ;
        const uint32_t* Bhs = sBh + st * BSZ;
        const uint32_t* Bls = sBl + st * BSZ;
#pragma unroll
        for (int ks = 0; ks < 2; ks++) {
            uint32_t ah[MT][4], al[MT][4], bh[NT][2], bl[NT][2];
            int kp0 = ks * 8 + tig, kp1 = kp0 + 4;
#pragma unroll
            for (int mt = 0; mt < MT; mt++) {
                int r = wm * WM + mt * 16 + group;
                ah[mt][0] = Ahs[kp0 * AS + r];     al[mt][0] = Als[kp0 * AS + r];
                ah[mt][1] = Ahs[kp0 * AS + r + 8]; al[mt][1] = Als[kp0 * AS + r + 8];
                ah[mt][2] = Ahs[kp1 * AS + r];     al[mt][2] = Als[kp1 * AS + r];
                ah[mt][3] = Ahs[kp1 * AS + r + 8]; al[mt][3] = Als[kp1 * AS + r + 8];
            }
#pragma unroll
            for (int nt = 0; nt < NT; nt++) {
                int c = wn * WN + nt * 8 + group;
                bh[nt][0] = Bhs[kp0 * BS + c];  bl[nt][0] = Bls[kp0 * BS + c];
                bh[nt][1] = Bhs[kp1 * BS + c];  bl[nt][1] = Bls[kp1 * BS + c];
            }
#pragma unroll
            for (int mt = 0; mt < MT; mt++)
#pragma unroll
                for (int nt = 0; nt < NT; nt++) {
                    mma16816(acc[mt][nt], ah[mt], bh[nt]);
                    mma16816(acc[mt][nt], al[mt], bh[nt]);
                    mma16816(acc[mt][nt], ah[mt], bl[nt]);
                }
        }
        __syncthreads();
        if (kpref < K) {
            int pst = st + STAGES - 1; if (pst >= STAGES) pst -= STAGES;
            cpStage(kpref, pst); kpref += 32;
        }
        asm volatile("cp.async.wait_group %0;" :: "n"(STAGES - 2));
        __syncthreads();
        if (++st == STAGES) st = 0;
    }

#pragma unroll
    for (int mt = 0; mt < MT; mt++) {
        int r = row0 + wm * WM + mt * 16 + group;
#pragma unroll
        for (int nt = 0; nt < NT; nt++) {
            int c = col0 + wn * WN + nt * 8 + tig * 2;
            float v00 = acc[mt][nt][0] * alpha;
            float v01 = acc[mt][nt][1] * alpha;
            float v10 = acc[mt][nt][2] * alpha;
            float v11 = acc[mt][nt][3] * alpha;
            if (doBias) {
                float2 bb = *reinterpret_cast<const float2*>(&bias[c]);
                v00 += bb.x; v01 += bb.y; v10 += bb.x; v11 += bb.y;
            }
            if (doRelu) {
                v00 = fmaxf(v00, 0.f); v01 = fmaxf(v01, 0.f);
                v10 = fmaxf(v10, 0.f); v11 = fmaxf(v11, 0.f);
            }
            *reinterpret_cast<float2*>(&Cb[(long long)r * ldc + c])       = make_float2(v00, v01);
            *reinterpret_cast<float2*>(&Cb[(long long)(r + 8) * ldc + c]) = make_float2(v10, v11);
        }
    }
}

// ---------------- fp32-A GEMM (for P@V; in-kernel A conversion) ----------------
template<int TBM, int TBN, int NTHREADS, int WARPS_M>
__global__ __launch_bounds__(NTHREADS)
void gemm_pk(const float* __restrict__ A,
             const uint32_t* __restrict__ BH, const uint32_t* __restrict__ BL,
             const float* __restrict__ bias, float* __restrict__ C,
             int K, int lda, int ldbp, int ldc,
             long long sAo, long long sAi, long long sBo, long long sBi,
             long long sCo, long long sCi, int Hsub,
             float alpha, int doBias, int doRelu)
{
    constexpr int WARPS   = NTHREADS / 32;
    constexpr int WARPS_N = WARPS / WARPS_M;
    constexpr int WM = TBM / WARPS_M;
    constexpr int WN = TBN / WARPS_N;
    constexpr int MT = WM / 16;
    constexpr int NT = WN / 8;
    constexpr int AS = TBM + 8;
    constexpr int BS = TBN + 8;
    constexpr int ASZ = 16 * AS;
    constexpr int BSZ = 16 * BS;
    constexpr int PF = TBM * 32 / (4 * NTHREADS);
    constexpr int BC = (16 * (TBN / 4)) / NTHREADS;

    extern __shared__ uint32_t smem[];
    uint32_t* sAh = smem;
    uint32_t* sAl = smem + 2 * ASZ;
    uint32_t* sBh = smem + 4 * ASZ;
    uint32_t* sBl = smem + 4 * ASZ + 2 * BSZ;

    int z = blockIdx.z;
    int zo = z / Hsub, zi = z % Hsub;
    const float*    Ab  = A  + zo * sAo + zi * sAi;
    const uint32_t* Bhb = BH + zo * sBo + zi * sBi;
    const uint32_t* Blb = BL + zo * sBo + zi * sBi;
    float*          Cb  = C  + zo * sCo + zi * sCi;

    int tid = threadIdx.x;
    int wid = tid >> 5, lane = tid & 31;
    int wm = wid % WARPS_M, wn = wid / WARPS_M;
    int group = lane >> 2, tig = lane & 3;
    int row0 = blockIdx.x * TBM;
    int col0 = blockIdx.y * TBN;

    float4 pf[PF];

    auto loadA = [&](int k0) {
#pragma unroll
        for (int i = 0; i < PF; i++) {
            int idx = tid + i * NTHREADS;
            int r = idx >> 3, c4 = idx & 7;
            pf[i] = *reinterpret_cast<const float4*>(
                Ab + (long long)(row0 + r) * lda + k0 + c4 * 4);
        }
    };
    auto cvtStoreA = [&](int st) {
        uint32_t* ah = sAh + st * ASZ;
        uint32_t* al = sAl + st * ASZ;
#pragma unroll
        for (int i = 0; i < PF; i++) {
            int idx = tid + i * NTHREADS;
            int r = idx >> 3, c4 = idx & 7;
            uint32_t h0, l0, h1, l1;
            cvt_pair(pf[i].x, pf[i].y, h0, l0);
            cvt_pair(pf[i].z, pf[i].w, h1, l1);
            ah[(c4*2    ) * AS + r] = h0;  al[(c4*2    ) * AS + r] = l0;
            ah[(c4*2 + 1) * AS + r] = h1;  al[(c4*2 + 1) * AS + r] = l1;
        }
    };
    auto cpB = [&](int k0, int st) {
        int kp0 = k0 >> 1;
        uint32_t bh0 = (uint32_t)__cvta_generic_to_shared(sBh + st * BSZ);
        uint32_t bl0 = (uint32_t)__cvta_generic_to_shared(sBl + st * BSZ);
#pragma unroll
        for (int j = 0; j < BC; j++) {
            int ci = tid + j * NTHREADS;
            int rr = ci / (TBN / 4), cc = ci % (TBN / 4);
            long long go = (long long)(kp0 + rr) * ldbp + col0 + cc * 4;
            uint32_t so = (rr * BS + cc * 4) * 4;
            cp_async16(bh0 + so, Bhb + go);
            cp_async16(bl0 + so, Blb + go);
        }
    };

    float acc[MT][NT][4];
#pragma unroll
    for (int i = 0; i < MT; i++)
#pragma unroll
        for (int j = 0; j < NT; j++)
#pragma unroll
            for (int t = 0; t < 4; t++) acc[i][j][t] = 0.f;

    loadA(0);
    cpB(0, 0); CP_COMMIT();
    cvtStoreA(0);
    CP_WAIT0();
    __syncthreads();

    int st = 0;
    for (int k0 = 0; k0 < K; k0 += 32) {
        bool has_next = (k0 + 32) < K;
        if (has_next) {
            loadA(k0 + 32);
            cpB(k0 + 32, st ^ 1); CP_COMMIT();
        }
        const uint32_t* Ahs = sAh + st * ASZ;
        const uint32_t* Als = sAl + st * ASZ;
        const uint32_t* Bhs = sBh + st * BSZ;
        const uint32_t* Bls = sBl + st * BSZ;
#pragma unroll
        for (int ks = 0; ks < 2; ks++) {
            uint32_t ah[MT][4], al[MT][4], bh[NT][2], bl[NT][2];
            int kp0 = ks * 8 + tig, kp1 = kp0 + 4;
#pragma unroll
            for (int mt = 0; mt < MT; mt++) {
                int r = wm * WM + mt * 16 + group;
                ah[mt][0] = Ahs[kp0 * AS + r];     al[mt][0] = Als[kp0 * AS + r];
                ah[mt][1] = Ahs[kp0 * AS + r + 8]; al[mt][1] = Als[kp0 * AS + r + 8];
                ah[mt][2] = Ahs[kp1 * AS + r];     al[mt][2] = Als[kp1 * AS + r];
                ah[mt][3] = Ahs[kp1 * AS + r + 8]; al[mt][3] = Als[kp1 * AS + r + 8];
            }
#pragma unroll
            for (int nt = 0; nt < NT; nt++) {
                int c = wn * WN + nt * 8 + group;
                bh[nt][0] = Bhs[kp0 * BS + c];  bl[nt][0] = Bls[kp0 * BS + c];
                bh[nt][1] = Bhs[kp1 * BS + c];  bl[nt][1] = Bls[kp1 * BS + c];
            }
#pragma unroll
            for (int mt = 0; mt < MT; mt++)
#pragma unroll
                for (int nt = 0; nt < NT; nt++) {
                    mma16816(acc[mt][nt], ah[mt], bh[nt]);
                    mma16816(acc[mt][nt], al[mt], bh[nt]);
                    mma16816(acc[mt][nt], ah[mt], bl[nt]);
                }
        }
        if (has_next) {
            cvtStoreA(st ^ 1);
            CP_WAIT0();
        }
        __syncthreads();
        st ^= 1;
    }

#pragma unroll
    for (int mt = 0; mt < MT; mt++) {
        int r = row0 + wm * WM + mt * 16 + group;
#pragma unroll
        for (int nt = 0; nt < NT; nt++) {
            int c = col0 + wn * WN + nt * 8 + tig * 2;
            float v00 = acc[mt][nt][0] * alpha;
            float v01 = acc[mt][nt][1] * alpha;
            float v10 = acc[mt][nt][2] * alpha;
            float v11 = acc[mt][nt][3] * alpha;
            if (doBias) {
                float2 bb = *reinterpret_cast<const float2*>(&bias[c]);
                v00 += bb.x; v01 += bb.y; v10 += bb.x; v11 += bb.y;
            }
            if (doRelu) {
                v00 = fmaxf(v00, 0.f); v01 = fmaxf(v01, 0.f);
                v10 = fmaxf(v10, 0.f); v11 = fmaxf(v11, 0.f);
            }
            *reinterpret_cast<float2*>(&Cb[(long long)r * ldc + c])       = make_float2(v00, v01);
            *reinterpret_cast<float2*>(&Cb[(long long)(r + 8) * ldc + c]) = make_float2(v10, v11);
        }
    }
}

// ---------------- scores softmax (L=512) ----------
__global__ __launch_bounds__(256)
void softmax_rows(float* __restrict__ P, int causal)
{
    long long row = blockIdx.x;
    float* p = P + row * (long long)Ss;
    int qpos = (int)(row % Ss);
    int t = threadIdx.x;
    __shared__ float red[256];

    float v0 = p[t], v1 = p[t + 256];
    if (causal) {
        if (t > qpos) v0 = -1e9f;
        if (t + 256 > qpos) v1 = -1e9f;
    }
    float mx = fmaxf(v0, v1);
    red[t] = mx; __syncthreads();
    for (int o = 128; o; o >>= 1) { if (t < o) red[t] = fmaxf(red[t], red[t + o]); __syncthreads(); }
    mx = red[0]; __syncthreads();
    float e0 = __expf(v0 - mx), e1 = __expf(v1 - mx);
    red[t] = e0 + e1; __syncthreads();
    for (int o = 128; o; o >>= 1) { if (t < o) red[t] += red[t + o]; __syncthreads(); }
    float inv = 1.0f / red[0];
    p[t] = e0 * inv;
    p[t + 256] = e1 * inv;
}

// ---------------- vocab softmax ----------
__global__ __launch_bounds__(1024)
void softmax_vocab(float* __restrict__ P)
{
    float* p = P + (long long)blockIdx.x * Vv;
    int t = threadIdx.x;
    __shared__ float red[32];
    float v[32];
    float mx = -3.0e38f;
#pragma unroll
    for (int i = 0; i < 32; i++) {
        int idx = t + i * 1024;
        v[i] = (idx < Vv) ? p[idx] : -3.0e38f;
        mx = fmaxf(mx, v[i]);
    }
    for (int o = 16; o; o >>= 1) mx = fmaxf(mx, __shfl_xor_sync(0xffffffffu, mx, o));
    if ((t & 31) == 0) red[t >> 5] = mx;
    __syncthreads();
    if (t < 32) {
        float m2 = red[t];
        for (int o = 16; o; o >>= 1) m2 = fmaxf(m2, __shfl_xor_sync(0xffffffffu, m2, o));
        if (t == 0) red[0] = m2;
    }
    __syncthreads();
    mx = red[0];
    __syncthreads();
    float sum = 0.f;
#pragma unroll
    for (int i = 0; i < 32; i++) { v[i] = __expf(v[i] - mx); sum += v[i]; }
    for (int o = 16; o; o >>= 1) sum += __shfl_xor_sync(0xffffffffu, sum, o);
    if ((t & 31) == 0) red[t >> 5] = sum;
    __syncthreads();
    if (t < 32) {
        float s2 = red[t];
        for (int o = 16; o; o >>= 1) s2 += __shfl_xor_sync(0xffffffffu, s2, o);
        if (t == 0) red[0] = s2;
    }
    __syncthreads();
    float inv = 1.0f / red[0];
#pragma unroll
    for (int i = 0; i < 32; i++) {
        int idx = t + i * 1024;
        if (idx < Vv) p[idx] = v[i] * inv;
    }
}

// ---------------- add + LayerNorm ----------
__global__ __launch_bounds__(256)
void add_ln_kernel(float* __restrict__ x, const float* __restrict__ sub)
{
    int row = blockIdx.x;
    float* xr = x + (long long)row * Dd;
    const float* sr = sub + (long long)row * Dd;
    int t = threadIdx.x;
    __shared__ float red[256];

    float v0 = xr[t] + sr[t];
    float v1 = xr[t + 256] + sr[t + 256];
    red[t] = v0 + v1; __syncthreads();
    for (int o = 128; o; o >>= 1) { if (t < o) red[t] += red[t + o]; __syncthreads(); }
    float mu = red[0] * (1.0f / 512.0f); __syncthreads();
    float d0 = v0 - mu, d1 = v1 - mu;
    red[t] = d0 * d0 + d1 * d1; __syncthreads();
    for (int o = 128; o; o >>= 1) { if (t < o) red[t] += red[t + o]; __syncthreads(); }
    float inv = rsqrtf(red[0] * (1.0f / 512.0f) + 1e-5f);
    xr[t] = d0 * inv;
    xr[t + 256] = d1 * inv;
}

// ---------------- embedding + PE ----------
__global__ __launch_bounds__(512)
void embed_pe_kernel(const int* __restrict__ tok, const float* __restrict__ emb,
                     float* __restrict__ out)
{
    int idx = blockIdx.x;
    int s = idx % Ss;
    int j = threadIdx.x;
    int tk = tok[idx];
    float ang = (float)s * powf(10000.0f, -2.0f * (float)j / 512.0f);
    float pe = (j & 1) ? cosf(ang) : sinf(ang);
    out[(long long)idx * Dd + j] = emb[(long long)tk * Dd + j] + pe;
}

// ---------------- host ----------------
static const int SM_PK64   = (4 * 2 * 16 * (64 + 8)) * 4;          // 36,864
static const int SM_AP64_2 = (4 * 2 * 16 * (64 + 8)) * 4;          // 36,864
static const int SM_AP64_4 = (4 * 4 * 16 * (64 + 8)) * 4;          // 73,728
static const int SM_AP128_3= (4 * 3 * 16 * (128 + 8)) * 4;         // 104,448

struct GPtrs {
    float *x, *y, *qkv, *attn, *tmp, *ffn, *scores;
    uint32_t *encWh, *encWl, *decSWh, *decSWl, *decCWh, *decCWl;
    uint32_t *eW1h, *eW1l, *eW2h, *eW2l, *dW1h, *dW1l, *dW2h, *dW2l;
    uint32_t *oWh, *oWl, *Kch, *Kcl, *Vch, *Vcl, *aTh, *aTl, *xeTh, *xeTl;
};

// one attention block; aT buffer gets reused (sequential stream ordering)
static void run_mha(GPtrs& G, const float* xq, const uint32_t* xkvTh, const uint32_t* xkvTl,
                    const uint32_t* wh, const uint32_t* wl, float* out, bool causal, bool self)
{
    const long long TD = (long long)TOK * Dd;
    // pack A for Q-projection (and K/V when self)
    convAT<<<dim3(TOK/32, Dd/32), 256>>>(xq, G.aTh, G.aTl, TOK, Dd);
    if (self) {
        dim3 g(TOK/64, Dd/64, 3);
        gemm_ap<64,64,128,2,4><<<g, 128, SM_AP64_4>>>(G.aTh, G.aTl, wh, wl, nullptr, G.qkv,
            Dd, TOK, Dd, Dd,
            0, 0, 0, DD2, 0, TD, 3, 1.0f, 0, 0);
    } else {
        dim3 gq(TOK/64, Dd/64, 1);
        gemm_ap<64,64,128,2,4><<<gq, 128, SM_AP64_4>>>(G.aTh, G.aTl, wh, wl, nullptr, G.qkv,
            Dd, TOK, Dd, Dd,
            0, 0, 0, 0, 0, 0, 1, 1.0f, 0, 0);
        dim3 gkv(TOK/64, Dd/64, 2);
        gemm_ap<64,64,128,2,4><<<gkv, 128, SM_AP64_4>>>(xkvTh, xkvTl, wh + DD2, wl + DD2,
            nullptr, G.qkv + TD,
            Dd, TOK, Dd, Dd,
            0, 0, 0, DD2, 0, TD, 2, 1.0f, 0, 0);
    }
    const float* q = G.qkv;
    const float* k = G.qkv + TD;
    const float* v = G.qkv + 2 * TD;

    convAT<<<dim3(TOK/32, Dd/32), 256>>>(k, G.Kch, G.Kcl, TOK, Dd);
    convB<<<dim3(Dd/256, TOK/2), 256>>>(v, G.Vch, G.Vcl, Dd);
    convAT<<<dim3(TOK/32, Dd/32), 256>>>(q, G.aTh, G.aTl, TOK, Dd);

    // scores = Q @ K^T / 8
    {
        dim3 g(Ss/64, Ss/64, Bn*Hh);
        gemm_ap<64,64,128,2,2><<<g, 128, SM_AP64_2>>>(G.aTh, G.aTl, G.Kch, G.Kcl, nullptr, G.scores,
            DKk, TOK, TOK, Ss,
            Ss, 32LL*TOK,
            Ss, 32LL*TOK,
            (long long)Hh*Ss*Ss, (long long)Ss*Ss,
            Hh, 0.125f, 0, 0);
    }
    softmax_rows<<<Bn*Hh*Ss, 256>>>(G.scores, causal ? 1 : 0);

    // attn = P @ V (fp32-A path)
    {
        dim3 g(Ss/64, DKk/64, Bn*Hh);
        gemm_pk<64,64,128,2><<<g, 128, SM_PK64>>>(G.scores, G.Vch, G.Vcl, nullptr, G.attn,
            Ss, Ss, Dd, Dd,
            (long long)Hh*Ss*Ss, (long long)Ss*Ss,
            (long long)(Ss/2)*Dd, DKk,
            (long long)Ss*Dd, DKk,
            Hh, 1.0f, 0, 0);
    }
    // output projection
    convAT<<<dim3(TOK/32, Dd/32), 256>>>(G.attn, G.aTh, G.aTl, TOK, Dd);
    {
        dim3 g(TOK/64, Dd/64, 1);
        gemm_ap<64,64,128,2,4><<<g, 128, SM_AP64_4>>>(G.aTh, G.aTl, wh + 3*DD2, wl + 3*DD2,
            nullptr, out, Dd, TOK, Dd, Dd,
            0, 0, 0, 0, 0, 0, 1, 1.0f, 0, 0);
    }
}

static void run_ffn(GPtrs& G, float* xact, const uint32_t* w1h, const uint32_t* w1l,
                    const float* b1, const uint32_t* w2h, const uint32_t* w2l, const float* b2)
{
    convAT<<<dim3(TOK/32, Dd/32), 256>>>(xact, G.aTh, G.aTl, TOK, Dd);
    {
        dim3 g(TOK/128, FFf/128, 1);
        gemm_ap<128,128,256,4,3><<<g, 256, SM_AP128_3>>>(G.aTh, G.aTl, w1h, w1l, b1, G.ffn,
            Dd, TOK, FFf, FFf,
            0, 0, 0, 0, 0, 0, 1, 1.0f, 1, 1);
    }
    convAT<<<dim3(TOK/32, FFf/32), 256>>>(G.ffn, G.aTh, G.aTl, TOK, FFf);
    {
        dim3 g(TOK/64, Dd/64, 1);
        gemm_ap<64,64,128,2,4><<<g, 128, SM_AP64_4>>>(G.aTh, G.aTl, w2h, w2l, b2, G.tmp,
            FFf, TOK, Dd, Dd,
            0, 0, 0, 0, 0, 0, 1, 1.0f, 1, 0);
    }
}

extern "C" void kernel_launch(void* const* d_in, const int* in_sizes, int n_in,
                              void* d_out, int out_size)
{
    const int*   src           = (const int*)  d_in[0];
    const int*   trg           = (const int*)  d_in[1];
    const float* src_emb       = (const float*)d_in[2];
    const float* trg_emb       = (const float*)d_in[3];
    const float* enc_qkvo      = (const float*)d_in[4];
    const float* enc_ffn_w1    = (const float*)d_in[5];
    const float* enc_ffn_b1    = (const float*)d_in[6];
    const float* enc_ffn_w2    = (const float*)d_in[7];
    const float* enc_ffn_b2    = (const float*)d_in[8];
    const float* dec_self_qkvo = (const float*)d_in[9];
    const float* dec_cross_qkvo= (const float*)d_in[10];
    const float* dec_ffn_w1    = (const float*)d_in[11];
    const float* dec_ffn_b1    = (const float*)d_in[12];
    const float* dec_ffn_w2    = (const float*)d_in[13];
    const float* dec_ffn_b2    = (const float*)d_in[14];
    const float* out_w         = (const float*)d_in[15];
    const float* out_b         = (const float*)d_in[16];
    float* out = (float*)d_out;

    cudaFuncSetAttribute(gemm_ap<64,64,128,2,4>,
                         cudaFuncAttributeMaxDynamicSharedMemorySize, SM_AP64_4);
    cudaFuncSetAttribute(gemm_ap<128,128,256,4,3>,
                         cudaFuncAttributeMaxDynamicSharedMemorySize, SM_AP128_3);

    GPtrs G;
    cudaGetSymbolAddress((void**)&G.x,      g_x);
    cudaGetSymbolAddress((void**)&G.y,      g_y);
    cudaGetSymbolAddress((void**)&G.qkv,    g_qkv);
    cudaGetSymbolAddress((void**)&G.attn,   g_attn);
    cudaGetSymbolAddress((void**)&G.tmp,    g_tmp);
    cudaGetSymbolAddress((void**)&G.ffn,    g_ffn);
    cudaGetSymbolAddress((void**)&G.scores, g_scores);
    cudaGetSymbolAddress((void**)&G.encWh,  g_encW_h);  cudaGetSymbolAddress((void**)&G.encWl, g_encW_l);
    cudaGetSymbolAddress((void**)&G.decSWh, g_decSW_h); cudaGetSymbolAddress((void**)&G.decSWl, g_decSW_l);
    cudaGetSymbolAddress((void**)&G.decCWh, g_decCW_h); cudaGetSymbolAddress((void**)&G.decCWl, g_decCW_l);
    cudaGetSymbolAddress((void**)&G.eW1h,   g_encW1_h); cudaGetSymbolAddress((void**)&G.eW1l, g_encW1_l);
    cudaGetSymbolAddress((void**)&G.eW2h,   g_encW2_h); cudaGetSymbolAddress((void**)&G.eW2l, g_encW2_l);
    cudaGetSymbolAddress((void**)&G.dW1h,   g_decW1_h); cudaGetSymbolAddress((void**)&G.dW1l, g_decW1_l);
    cudaGetSymbolAddress((void**)&G.dW2h,   g_decW2_h); cudaGetSymbolAddress((void**)&G.dW2l, g_decW2_l);
    cudaGetSymbolAddress((void**)&G.oWh,    g_outW_h);  cudaGetSymbolAddress((void**)&G.oWl, g_outW_l);
    cudaGetSymbolAddress((void**)&G.Kch,    g_Kc_h);    cudaGetSymbolAddress((void**)&G.Kcl, g_Kc_l);
    cudaGetSymbolAddress((void**)&G.Vch,    g_Vc_h);    cudaGetSymbolAddress((void**)&G.Vcl, g_Vc_l);
    cudaGetSymbolAddress((void**)&G.aTh,    g_aT_h);    cudaGetSymbolAddress((void**)&G.aTl, g_aT_l);
    cudaGetSymbolAddress((void**)&G.xeTh,   g_xeT_h);   cudaGetSymbolAddress((void**)&G.xeTl, g_xeT_l);

    // weight conversions (once per call)
    convB<<<dim3(Dd / 256,  24 * Dd / 2), 256>>>(enc_qkvo,       G.encWh, G.encWl, Dd);
    convB<<<dim3(Dd / 256,  24 * Dd / 2), 256>>>(dec_self_qkvo,  G.decSWh, G.decSWl, Dd);
    convB<<<dim3(Dd / 256,  24 * Dd / 2), 256>>>(dec_cross_qkvo, G.decCWh, G.decCWl, Dd);
    convB<<<dim3(FFf / 256, Nl * Dd / 2), 256>>>(enc_ffn_w1, G.eW1h, G.eW1l, FFf);
    convB<<<dim3(Dd / 256,  Nl * FFf / 2), 256>>>(enc_ffn_w2, G.eW2h, G.eW2l, Dd);
    convB<<<dim3(FFf / 256, Nl * Dd / 2), 256>>>(dec_ffn_w1, G.dW1h, G.dW1l, FFf);
    convB<<<dim3(Dd / 256,  Nl * FFf / 2), 256>>>(dec_ffn_w2, G.dW2h, G.dW2l, Dd);
    convB<<<dim3(Vv / 256,  Dd / 2), 256>>>(out_w, G.oWh, G.oWl, Vv);

    embed_pe_kernel<<<TOK, 512>>>(src, src_emb, G.x);
    embed_pe_kernel<<<TOK, 512>>>(trg, trg_emb, G.y);

    // ---------------- Encoder ----------------
    for (int i = 0; i < Nl; i++) {
        run_mha(G, G.x, nullptr, nullptr,
                G.encWh + (long long)i * 4 * DD2, G.encWl + (long long)i * 4 * DD2,
                G.tmp, false, true);
        add_ln_kernel<<<TOK, 256>>>(G.x, G.tmp);
        run_ffn(G, G.x,
                G.eW1h + (long long)i * W1SZ, G.eW1l + (long long)i * W1SZ,
                enc_ffn_b1 + (long long)i * FFf,
                G.eW2h + (long long)i * W1SZ, G.eW2l + (long long)i * W1SZ,
                enc_ffn_b2 + (long long)i * Dd);
        add_ln_kernel<<<TOK, 256>>>(G.x, G.tmp);
    }

    // pack encoder output once for all cross-attention layers
    convAT<<<dim3(TOK/32, Dd/32), 256>>>(G.x, G.xeTh, G.xeTl, TOK, Dd);

    // ---------------- Decoder ----------------
    for (int i = 0; i < Nl; i++) {
        run_mha(G, G.y, nullptr, nullptr,
                G.decSWh + (long long)i * 4 * DD2, G.decSWl + (long long)i * 4 * DD2,
                G.tmp, true, true);
        add_ln_kernel<<<TOK, 256>>>(G.y, G.tmp);

        run_mha(G, G.y, G.xeTh, G.xeTl,
                G.decCWh + (long long)i * 4 * DD2, G.decCWl + (long long)i * 4 * DD2,
                G.tmp, false, false);
        add_ln_kernel<<<TOK, 256>>>(G.y, G.tmp);

        run_ffn(G, G.y,
                G.dW1h + (long long)i * W1SZ, G.dW1l + (long long)i * W1SZ,
                dec_ffn_b1 + (long long)i * FFf,
                G.dW2h + (long long)i * W1SZ, G.dW2l + (long long)i * W1SZ,
                dec_ffn_b2 + (long long)i * Dd);
        add_ln_kernel<<<TOK, 256>>>(G.y, G.tmp);
    }

    // ---------------- Output projection + vocab softmax ----------------
    convAT<<<dim3(TOK/32, Dd/32), 256>>>(G.y, G.aTh, G.aTl, TOK, Dd);
    {
        dim3 g(TOK/128, Vv/128, 1);
        gemm_ap<128,128,256,4,3><<<g, 256, SM_AP128_3>>>(G.aTh, G.aTl, G.oWh, G.oWl, out_b, out,
            Dd, TOK, Vv, Vv,
            0, 0, 0, 0, 0, 0, 1, 1.0f, 1, 0);
    }
    softmax_vocab<<<TOK, 1024>>>(out);
}

// round 7
// speedup vs baseline: 2.8447x; 1.1916x over previous
#include <cuda_runtime.h>
#include <cuda_bf16.h>
#include <math.h>
#include <stdint.h>

#define Bn   4
#define Ss   512
#define Dd   512
#define Hh   8
#define DKk  64
#define Nl   6
#define Vv   32000
#define FFf  2048
#define TOK  (Bn*Ss)

// ---------------- fp32 scratch ----------------
__device__ __align__(16) float g_x[TOK*Dd];
__device__ __align__(16) float g_y[TOK*Dd];
__device__ __align__(16) float g_v[TOK*Dd];
__device__ __align__(16) float g_tmp[TOK*Dd];

// ---------------- packed bf16x2 hi/lo ----------------
#define DD2  (Dd*Dd/2)
__device__ __align__(16) uint32_t g_encW_h[24*DD2], g_encW_l[24*DD2];
__device__ __align__(16) uint32_t g_decSW_h[24*DD2], g_decSW_l[24*DD2];
__device__ __align__(16) uint32_t g_decCW_h[24*DD2], g_decCW_l[24*DD2];
#define W1SZ (Dd*FFf/2)
__device__ __align__(16) uint32_t g_encW1_h[Nl*W1SZ], g_encW1_l[Nl*W1SZ];
__device__ __align__(16) uint32_t g_encW2_h[Nl*W1SZ], g_encW2_l[Nl*W1SZ];
__device__ __align__(16) uint32_t g_decW1_h[Nl*W1SZ], g_decW1_l[Nl*W1SZ];
__device__ __align__(16) uint32_t g_decW2_h[Nl*W1SZ], g_decW2_l[Nl*W1SZ];
#define OWSZ (Dd*Vv/2)
__device__ __align__(16) uint32_t g_outW_h[OWSZ], g_outW_l[OWSZ];
#define KVC  (TOK*Dd/2)
__device__ __align__(16) uint32_t g_xT_h[KVC],  g_xT_l[KVC];      // activation^T packed
__device__ __align__(16) uint32_t g_qkT_h[2*KVC], g_qkT_l[2*KVC]; // q^T | k^T
__device__ __align__(16) uint32_t g_vP_h[KVC],  g_vP_l[KVC];      // v row-pair packed
__device__ __align__(16) uint32_t g_oT_h[KVC],  g_oT_l[KVC];      // attn out^T packed
__device__ __align__(16) uint32_t g_xeT_h[KVC], g_xeT_l[KVC];     // encoder out^T packed
#define FTSZ ((FFf/2)*TOK)
__device__ __align__(16) uint32_t g_fT_h[FTSZ], g_fT_l[FTSZ];     // ffn hidden^T packed

// ---------------- helpers ----------------
__device__ __forceinline__ void cvt_pair(float x0, float x1, uint32_t& hi, uint32_t& lo)
{
    uint32_t h;
    asm("cvt.rn.bf16x2.f32 %0, %1, %2;" : "=r"(h) : "f"(x1), "f"(x0));
    __nv_bfloat162 hb = *reinterpret_cast<__nv_bfloat162*>(&h);
    float r0 = x0 - __bfloat162float(hb.x);
    float r1 = x1 - __bfloat162float(hb.y);
    uint32_t l;
    asm("cvt.rn.bf16x2.f32 %0, %1, %2;" : "=r"(l) : "f"(r1), "f"(r0));
    hi = h; lo = l;
}

__device__ __forceinline__ uint32_t mulbf2(uint32_t a, uint32_t b)
{
    uint32_t d; asm("mul.rn.bf16x2 %0,%1,%2;" : "=r"(d) : "r"(a), "r"(b)); return d;
}

__device__ __forceinline__ void mma16816(float* c, const uint32_t* a, const uint32_t* b)
{
    asm volatile(
        "mma.sync.aligned.m16n8k16.row.col.f32.bf16.bf16.f32 "
        "{%0,%1,%2,%3}, {%4,%5,%6,%7}, {%8,%9}, {%0,%1,%2,%3};\n"
        : "+f"(c[0]), "+f"(c[1]), "+f"(c[2]), "+f"(c[3])
        : "r"(a[0]), "r"(a[1]), "r"(a[2]), "r"(a[3]), "r"(b[0]), "r"(b[1]));
}

__device__ __forceinline__ void cp_async16(uint32_t s, const void* g)
{
    asm volatile("cp.async.cg.shared.global [%0], [%1], 16;" :: "r"(s), "l"(g));
}
#define CP_COMMIT() asm volatile("cp.async.commit_group;")

// exact wait: ensure at most n commit-groups remain pending
__device__ __forceinline__ void cp_wait_n(int n)
{
    switch (n) {
    case 0: asm volatile("cp.async.wait_group 0;"); break;
    case 1: asm volatile("cp.async.wait_group 1;"); break;
    case 2: asm volatile("cp.async.wait_group 2;"); break;
    default: asm volatile("cp.async.wait_group 3;"); break;
    }
}

// ---------------- conversion kernels ----------------
__global__ __launch_bounds__(256)
void convB(const float* __restrict__ W, uint32_t* __restrict__ H,
           uint32_t* __restrict__ L, int C)
{
    long long kp = blockIdx.y;
    int c = blockIdx.x * 256 + threadIdx.x;
    float a = W[(2*kp) * (long long)C + c];
    float b = W[(2*kp+1) * (long long)C + c];
    uint32_t h, l; cvt_pair(a, b, h, l);
    long long o = kp * C + c;
    H[o] = h; L[o] = l;
}

__global__ __launch_bounds__(256)
void convAT(const float* __restrict__ X, uint32_t* __restrict__ H,
            uint32_t* __restrict__ L, int Mdim, int Kdim)
{
    __shared__ float s[32][33];
    int m0 = blockIdx.x * 32, k0 = blockIdx.y * 32;
    int tx = threadIdx.x & 31, ty = threadIdx.x >> 5;
#pragma unroll
    for (int i = 0; i < 4; i++) {
        int m = ty + i * 8;
        s[m][tx] = X[(long long)(m0 + m) * Kdim + k0 + tx];
    }
    __syncthreads();
    int om = threadIdx.x & 31, okp = threadIdx.x >> 5;
#pragma unroll
    for (int i = 0; i < 2; i++) {
        int kp = okp + i * 8;
        uint32_t h, l;
        cvt_pair(s[om][2*kp], s[om][2*kp+1], h, l);
        long long o = (long long)(k0/2 + kp) * Mdim + m0 + om;
        H[o] = h; L[o] = l;
    }
}

// ---------------- all-packed GEMM ----------------
// PACKT=0: C fp32 row-major. PACKT=1: write bf16x2 hi/lo transposed-packed [N/2][ldc]
template<int TBM, int TBN, int NTHREADS, int WARPS_M, int STAGES, int PACKT>
__global__ __launch_bounds__(NTHREADS)
void gemm_ap(const uint32_t* __restrict__ AH, const uint32_t* __restrict__ AL,
             const uint32_t* __restrict__ BH, const uint32_t* __restrict__ BL,
             const float* __restrict__ bias, float* __restrict__ C,
             uint32_t* __restrict__ CH, uint32_t* __restrict__ CL,
             int K, int ldap, int ldbp, int ldc,
             long long sAo, long long sAi, long long sBo, long long sBi,
             long long sCo, long long sCi, int Hsub,
             float alpha, int doBias, int doRelu)
{
    constexpr int WARPS   = NTHREADS / 32;
    constexpr int WARPS_N = WARPS / WARPS_M;
    constexpr int WM = TBM / WARPS_M;
    constexpr int WN = TBN / WARPS_N;
    constexpr int MT = WM / 16;
    constexpr int NT = WN / 8;
    constexpr int AS = TBM + 8;
    constexpr int BS = TBN + 8;
    constexpr int ASZ = 16 * AS;
    constexpr int BSZ = 16 * BS;
    constexpr int AC = (16 * (TBM / 4)) / NTHREADS;
    constexpr int BC = (16 * (TBN / 4)) / NTHREADS;

    extern __shared__ uint32_t smem[];
    uint32_t* sAh = smem;
    uint32_t* sAl = smem + STAGES * ASZ;
    uint32_t* sBh = smem + 2 * STAGES * ASZ;
    uint32_t* sBl = smem + 2 * STAGES * ASZ + STAGES * BSZ;

    int z = blockIdx.z;
    int zo = z / Hsub, zi = z % Hsub;
    const uint32_t* Ahb = AH + zo * sAo + zi * sAi;
    const uint32_t* Alb = AL + zo * sAo + zi * sAi;
    const uint32_t* Bhb = BH + zo * sBo + zi * sBi;
    const uint32_t* Blb = BL + zo * sBo + zi * sBi;
    float*    Cb  = PACKT ? nullptr : (C + zo * sCo + zi * sCi);
    uint32_t* CHb = PACKT ? (CH + zo * sCo + zi * sCi) : nullptr;
    uint32_t* CLb = PACKT ? (CL + zo * sCo + zi * sCi) : nullptr;

    int tid = threadIdx.x;
    int wid = tid >> 5, lane = tid & 31;
    int wm = wid % WARPS_M, wn = wid / WARPS_M;
    int group = lane >> 2, tig = lane & 3;
    int row0 = blockIdx.x * TBM;
    int col0 = blockIdx.y * TBN;

    auto cpStage = [&](int k0, int st) {
        int kp0 = k0 >> 1;
        uint32_t ah0 = (uint32_t)__cvta_generic_to_shared(sAh + st * ASZ);
        uint32_t al0 = (uint32_t)__cvta_generic_to_shared(sAl + st * ASZ);
#pragma unroll
        for (int j = 0; j < AC; j++) {
            int ci = tid + j * NTHREADS;
            int rr = ci / (TBM / 4), cc = ci % (TBM / 4);
            long long go = (long long)(kp0 + rr) * ldap + row0 + cc * 4;
            uint32_t so = (rr * AS + cc * 4) * 4;
            cp_async16(ah0 + so, Ahb + go);
            cp_async16(al0 + so, Alb + go);
        }
        uint32_t bh0 = (uint32_t)__cvta_generic_to_shared(sBh + st * BSZ);
        uint32_t bl0 = (uint32_t)__cvta_generic_to_shared(sBl + st * BSZ);
#pragma unroll
        for (int j = 0; j < BC; j++) {
            int ci = tid + j * NTHREADS;
            int rr = ci / (TBN / 4), cc = ci % (TBN / 4);
            long long go = (long long)(kp0 + rr) * ldbp + col0 + cc * 4;
            uint32_t so = (rr * BS + cc * 4) * 4;
            cp_async16(bh0 + so, Bhb + go);
            cp_async16(bl0 + so, Blb + go);
        }
        CP_COMMIT();
    };

    float acc[MT][NT][4];
#pragma unroll
    for (int i = 0; i < MT; i++)
#pragma unroll
        for (int j = 0; j < NT; j++)
#pragma unroll
            for (int t = 0; t < 4; t++) acc[i][j][t] = 0.f;

    int kpref = 0;
#pragma unroll
    for (int s = 0; s < STAGES - 1; s++) { cpStage(kpref, s); kpref += 32; }

    int st = 0;
    for (int k0 = 0; k0 < K; k0 += 32) {
        // issue next stage first (into the stage consumed STAGES-1 iters ago)
        if (kpref < K) {
            cpStage(kpref, (kpref >> 5) % STAGES);
            kpref += 32;
        }
        // exact wait: inflight unconsumed groups = (kpref - k0)/32; need oldest complete
        cp_wait_n(((kpref - k0) >> 5) - 1);
        __syncthreads();

        const uint32_t* Ahs = sAh + st * ASZ;
        const uint32_t* Als = sAl + st * ASZ;
        const uint32_t* Bhs = sBh + st * BSZ;
        const uint32_t* Bls = sBl + st * BSZ;
#pragma unroll
        for (int ks = 0; ks < 2; ks++) {
            uint32_t ah[MT][4], al[MT][4], bh[NT][2], bl[NT][2];
            int kp0 = ks * 8 + tig, kp1 = kp0 + 4;
#pragma unroll
            for (int mt = 0; mt < MT; mt++) {
                int r = wm * WM + mt * 16 + group;
                ah[mt][0] = Ahs[kp0 * AS + r];     al[mt][0] = Als[kp0 * AS + r];
                ah[mt][1] = Ahs[kp0 * AS + r + 8]; al[mt][1] = Als[kp0 * AS + r + 8];
                ah[mt][2] = Ahs[kp1 * AS + r];     al[mt][2] = Als[kp1 * AS + r];
                ah[mt][3] = Ahs[kp1 * AS + r + 8]; al[mt][3] = Als[kp1 * AS + r + 8];
            }
#pragma unroll
            for (int nt = 0; nt < NT; nt++) {
                int c = wn * WN + nt * 8 + group;
                bh[nt][0] = Bhs[kp0 * BS + c];  bl[nt][0] = Bls[kp0 * BS + c];
                bh[nt][1] = Bhs[kp1 * BS + c];  bl[nt][1] = Bls[kp1 * BS + c];
            }
#pragma unroll
            for (int mt = 0; mt < MT; mt++)
#pragma unroll
                for (int nt = 0; nt < NT; nt++) {
                    mma16816(acc[mt][nt], ah[mt], bh[nt]);
                    mma16816(acc[mt][nt], al[mt], bh[nt]);
                    mma16816(acc[mt][nt], ah[mt], bl[nt]);
                }
        }
        __syncthreads();
        if (++st == STAGES) st = 0;
    }

#pragma unroll
    for (int mt = 0; mt < MT; mt++) {
        int r = row0 + wm * WM + mt * 16 + group;
#pragma unroll
        for (int nt = 0; nt < NT; nt++) {
            int c = col0 + wn * WN + nt * 8 + tig * 2;
            float v00 = acc[mt][nt][0] * alpha;
            float v01 = acc[mt][nt][1] * alpha;
            float v10 = acc[mt][nt][2] * alpha;
            float v11 = acc[mt][nt][3] * alpha;
            if (doBias) {
                float2 bb = *reinterpret_cast<const float2*>(&bias[c]);
                v00 += bb.x; v01 += bb.y; v10 += bb.x; v11 += bb.y;
            }
            if (doRelu) {
                v00 = fmaxf(v00, 0.f); v01 = fmaxf(v01, 0.f);
                v10 = fmaxf(v10, 0.f); v11 = fmaxf(v11, 0.f);
            }
            if (PACKT) {
                long long base = (long long)(c >> 1) * ldc + r;
                uint32_t h, l;
                cvt_pair(v00, v01, h, l); CHb[base] = h;     CLb[base] = l;
                cvt_pair(v10, v11, h, l); CHb[base + 8] = h; CLb[base + 8] = l;
            } else {
                *reinterpret_cast<float2*>(&Cb[(long long)r * ldc + c])       = make_float2(v00, v01);
                *reinterpret_cast<float2*>(&Cb[(long long)(r + 8) * ldc + c]) = make_float2(v10, v11);
            }
        }
    }
}

// ---------------- fused flash attention ----------------
#define FA_STRIDE 68
#define FA_TSZ (32 * FA_STRIDE)
__global__ __launch_bounds__(128)
void flash_attn(const uint32_t* __restrict__ Qh, const uint32_t* __restrict__ Ql,
                const uint32_t* __restrict__ Kh, const uint32_t* __restrict__ Kl,
                const uint32_t* __restrict__ Vh, const uint32_t* __restrict__ Vl,
                uint32_t* __restrict__ Oh, uint32_t* __restrict__ Ol, int causal)
{
    extern __shared__ uint32_t smem[];
    uint32_t* sKh = smem;
    uint32_t* sKl = smem + 2 * FA_TSZ;
    uint32_t* sVh = smem + 4 * FA_TSZ;
    uint32_t* sVl = smem + 6 * FA_TSZ;

    int qb = blockIdx.x;
    int b  = blockIdx.y / Hh;
    int h  = blockIdx.y % Hh;
    int tid = threadIdx.x;
    int wid = tid >> 5, lane = tid & 31;
    int group = lane >> 2, tig = lane & 3;
    int tokBase = b * Ss + qb * 64 + wid * 16;

    uint32_t qh[4][4], ql[4][4];
    const uint32_t SC = 0x3E003E00u;  // bf16x2(0.125, 0.125), exact
#pragma unroll
    for (int ks = 0; ks < 4; ks++) {
        int kpa = h * 32 + ks * 8 + tig;
        long long b0 = (long long)kpa * TOK + tokBase + group;
        long long b2 = (long long)(kpa + 4) * TOK + tokBase + group;
        qh[ks][0] = mulbf2(Qh[b0], SC);     ql[ks][0] = mulbf2(Ql[b0], SC);
        qh[ks][1] = mulbf2(Qh[b0 + 8], SC); ql[ks][1] = mulbf2(Ql[b0 + 8], SC);
        qh[ks][2] = mulbf2(Qh[b2], SC);     ql[ks][2] = mulbf2(Ql[b2], SC);
        qh[ks][3] = mulbf2(Qh[b2 + 8], SC); ql[ks][3] = mulbf2(Ql[b2 + 8], SC);
    }

    float m0 = -INFINITY, m1 = -INFINITY, l0 = 0.f, l1 = 0.f;
    float acc_o[8][4];
#pragma unroll
    for (int nt = 0; nt < 8; nt++)
#pragma unroll
        for (int t = 0; t < 4; t++) acc_o[nt][t] = 0.f;

    int nkb = causal ? (qb + 1) : (Ss / 64);

    auto cpStage = [&](int kb, int stg) {
        uint32_t kh0 = (uint32_t)__cvta_generic_to_shared(sKh + stg * FA_TSZ);
        uint32_t kl0 = (uint32_t)__cvta_generic_to_shared(sKl + stg * FA_TSZ);
        uint32_t vh0 = (uint32_t)__cvta_generic_to_shared(sVh + stg * FA_TSZ);
        uint32_t vl0 = (uint32_t)__cvta_generic_to_shared(sVl + stg * FA_TSZ);
#pragma unroll
        for (int i = 0; i < 4; i++) {
            int idx = tid + i * 128;
            int row = idx >> 4, c4 = idx & 15;
            uint32_t so = (row * FA_STRIDE + c4 * 4) * 4;
            long long gK = (long long)(h * 32 + row) * TOK + b * Ss + kb * 64 + c4 * 4;
            cp_async16(kh0 + so, Kh + gK);
            cp_async16(kl0 + so, Kl + gK);
            long long gV = (long long)(b * (Ss / 2) + kb * 32 + row) * Dd + h * 64 + c4 * 4;
            cp_async16(vh0 + so, Vh + gV);
            cp_async16(vl0 + so, Vl + gV);
        }
        CP_COMMIT();
    };

    cpStage(0, 0);
    for (int kb = 0; kb < nkb; kb++) {
        if (kb + 1 < nkb) {
            cpStage(kb + 1, (kb + 1) & 1);
            asm volatile("cp.async.wait_group 1;");
        } else {
            asm volatile("cp.async.wait_group 0;");
        }
        __syncthreads();
        int stg = kb & 1;
        const uint32_t* Ksh = sKh + stg * FA_TSZ;
        const uint32_t* Ksl = sKl + stg * FA_TSZ;
        const uint32_t* Vsh = sVh + stg * FA_TSZ;
        const uint32_t* Vsl = sVl + stg * FA_TSZ;

        float s[8][4];
#pragma unroll
        for (int nt = 0; nt < 8; nt++)
#pragma unroll
            for (int t = 0; t < 4; t++) s[nt][t] = 0.f;
#pragma unroll
        for (int ks = 0; ks < 4; ks++) {
            int r0 = (ks * 8 + tig) * FA_STRIDE, r1 = r0 + 4 * FA_STRIDE;
            uint32_t bhf[8][2], blf[8][2];
#pragma unroll
            for (int nt = 0; nt < 8; nt++) {
                int c = nt * 8 + group;
                bhf[nt][0] = Ksh[r0 + c]; bhf[nt][1] = Ksh[r1 + c];
                blf[nt][0] = Ksl[r0 + c]; blf[nt][1] = Ksl[r1 + c];
            }
#pragma unroll
            for (int nt = 0; nt < 8; nt++) {
                mma16816(s[nt], qh[ks], bhf[nt]);
                mma16816(s[nt], ql[ks], bhf[nt]);
                mma16816(s[nt], qh[ks], blf[nt]);
            }
        }

        if (causal && kb == qb) {
            int r0 = wid * 16 + group, r1 = r0 + 8;
#pragma unroll
            for (int nt = 0; nt < 8; nt++) {
                int c0 = nt * 8 + tig * 2;
                if (c0     > r0) s[nt][0] = -1e9f;
                if (c0 + 1 > r0) s[nt][1] = -1e9f;
                if (c0     > r1) s[nt][2] = -1e9f;
                if (c0 + 1 > r1) s[nt][3] = -1e9f;
            }
        }

        float bm0 = -INFINITY, bm1 = -INFINITY;
#pragma unroll
        for (int nt = 0; nt < 8; nt++) {
            bm0 = fmaxf(bm0, fmaxf(s[nt][0], s[nt][1]));
            bm1 = fmaxf(bm1, fmaxf(s[nt][2], s[nt][3]));
        }
        bm0 = fmaxf(bm0, __shfl_xor_sync(0xffffffffu, bm0, 1));
        bm0 = fmaxf(bm0, __shfl_xor_sync(0xffffffffu, bm0, 2));
        bm1 = fmaxf(bm1, __shfl_xor_sync(0xffffffffu, bm1, 1));
        bm1 = fmaxf(bm1, __shfl_xor_sync(0xffffffffu, bm1, 2));
        float nm0 = fmaxf(m0, bm0), nm1 = fmaxf(m1, bm1);
        float a0f = __expf(m0 - nm0), a1f = __expf(m1 - nm1);
        m0 = nm0; m1 = nm1;
        float rs0 = 0.f, rs1 = 0.f;
#pragma unroll
        for (int nt = 0; nt < 8; nt++) {
            s[nt][0] = __expf(s[nt][0] - nm0);
            s[nt][1] = __expf(s[nt][1] - nm0);
            s[nt][2] = __expf(s[nt][2] - nm1);
            s[nt][3] = __expf(s[nt][3] - nm1);
            rs0 += s[nt][0] + s[nt][1];
            rs1 += s[nt][2] + s[nt][3];
        }
        rs0 += __shfl_xor_sync(0xffffffffu, rs0, 1);
        rs0 += __shfl_xor_sync(0xffffffffu, rs0, 2);
        rs1 += __shfl_xor_sync(0xffffffffu, rs1, 1);
        rs1 += __shfl_xor_sync(0xffffffffu, rs1, 2);
        l0 = l0 * a0f + rs0;
        l1 = l1 * a1f + rs1;
#pragma unroll
        for (int nt = 0; nt < 8; nt++) {
            acc_o[nt][0] *= a0f; acc_o[nt][1] *= a0f;
            acc_o[nt][2] *= a1f; acc_o[nt][3] *= a1f;
        }

        uint32_t ph[4][4], pl[4][4];
#pragma unroll
        for (int j = 0; j < 4; j++) {
            cvt_pair(s[2*j  ][0], s[2*j  ][1], ph[j][0], pl[j][0]);
            cvt_pair(s[2*j  ][2], s[2*j  ][3], ph[j][1], pl[j][1]);
            cvt_pair(s[2*j+1][0], s[2*j+1][1], ph[j][2], pl[j][2]);
            cvt_pair(s[2*j+1][2], s[2*j+1][3], ph[j][3], pl[j][3]);
        }

#pragma unroll
        for (int j = 0; j < 4; j++) {
            int r0 = (j * 8 + tig) * FA_STRIDE, r1 = r0 + 4 * FA_STRIDE;
            uint32_t vbh[8][2], vbl[8][2];
#pragma unroll
            for (int nt = 0; nt < 8; nt++) {
                int c = nt * 8 + group;
                vbh[nt][0] = Vsh[r0 + c]; vbh[nt][1] = Vsh[r1 + c];
                vbl[nt][0] = Vsl[r0 + c]; vbl[nt][1] = Vsl[r1 + c];
            }
#pragma unroll
            for (int nt = 0; nt < 8; nt++) {
                mma16816(acc_o[nt], ph[j], vbh[nt]);
                mma16816(acc_o[nt], pl[j], vbh[nt]);
                mma16816(acc_o[nt], ph[j], vbl[nt]);
            }
        }
        __syncthreads();
    }

    float inv0 = 1.0f / l0, inv1 = 1.0f / l1;
#pragma unroll
    for (int nt = 0; nt < 8; nt++) {
        int cp = h * 32 + nt * 4 + tig;
        long long bo = (long long)cp * TOK + tokBase + group;
        uint32_t hh, ll;
        cvt_pair(acc_o[nt][0] * inv0, acc_o[nt][1] * inv0, hh, ll);
        Oh[bo] = hh; Ol[bo] = ll;
        cvt_pair(acc_o[nt][2] * inv1, acc_o[nt][3] * inv1, hh, ll);
        Oh[bo + 8] = hh; Ol[bo + 8] = ll;
    }
}

// ---------------- vocab softmax ----------
__global__ __launch_bounds__(1024)
void softmax_vocab(float* __restrict__ P)
{
    float* p = P + (long long)blockIdx.x * Vv;
    int t = threadIdx.x;
    __shared__ float red[32];
    float v[32];
    float mx = -3.0e38f;
#pragma unroll
    for (int i = 0; i < 32; i++) {
        int idx = t + i * 1024;
        v[i] = (idx < Vv) ? p[idx] : -3.0e38f;
        mx = fmaxf(mx, v[i]);
    }
    for (int o = 16; o; o >>= 1) mx = fmaxf(mx, __shfl_xor_sync(0xffffffffu, mx, o));
    if ((t & 31) == 0) red[t >> 5] = mx;
    __syncthreads();
    if (t < 32) {
        float m2 = red[t];
        for (int o = 16; o; o >>= 1) m2 = fmaxf(m2, __shfl_xor_sync(0xffffffffu, m2, o));
        if (t == 0) red[0] = m2;
    }
    __syncthreads();
    mx = red[0];
    __syncthreads();
    float sum = 0.f;
#pragma unroll
    for (int i = 0; i < 32; i++) { v[i] = __expf(v[i] - mx); sum += v[i]; }
    for (int o = 16; o; o >>= 1) sum += __shfl_xor_sync(0xffffffffu, sum, o);
    if ((t & 31) == 0) red[t >> 5] = sum;
    __syncthreads();
    if (t < 32) {
        float s2 = red[t];
        for (int o = 16; o; o >>= 1) s2 += __shfl_xor_sync(0xffffffffu, s2, o);
        if (t == 0) red[0] = s2;
    }
    __syncthreads();
    float inv = 1.0f / red[0];
#pragma unroll
    for (int i = 0; i < 32; i++) {
        int idx = t + i * 1024;
        if (idx < Vv) p[idx] = v[i] * inv;
    }
}

// ---------------- add + LayerNorm ----------
__global__ __launch_bounds__(256)
void add_ln_kernel(float* __restrict__ x, const float* __restrict__ sub)
{
    int row = blockIdx.x;
    float* xr = x + (long long)row * Dd;
    const float* sr = sub + (long long)row * Dd;
    int t = threadIdx.x;
    __shared__ float red[256];

    float v0 = xr[t] + sr[t];
    float v1 = xr[t + 256] + sr[t + 256];
    red[t] = v0 + v1; __syncthreads();
    for (int o = 128; o; o >>= 1) { if (t < o) red[t] += red[t + o]; __syncthreads(); }
    float mu = red[0] * (1.0f / 512.0f); __syncthreads();
    float d0 = v0 - mu, d1 = v1 - mu;
    red[t] = d0 * d0 + d1 * d1; __syncthreads();
    for (int o = 128; o; o >>= 1) { if (t < o) red[t] += red[t + o]; __syncthreads(); }
    float inv = rsqrtf(red[0] * (1.0f / 512.0f) + 1e-5f);
    xr[t] = d0 * inv;
    xr[t + 256] = d1 * inv;
}

// ---------------- embedding + PE ----------
__global__ __launch_bounds__(512)
void embed_pe_kernel(const int* __restrict__ tok, const float* __restrict__ emb,
                     float* __restrict__ out)
{
    int idx = blockIdx.x;
    int s = idx % Ss;
    int j = threadIdx.x;
    int tk = tok[idx];
    float ang = (float)s * powf(10000.0f, -2.0f * (float)j / 512.0f);
    float pe = (j & 1) ? cosf(ang) : sinf(ang);
    out[(long long)idx * Dd + j] = emb[(long long)tk * Dd + j] + pe;
}

// ---------------- host ----------------
static const int SM_AP64_4  = (4 * 4 * 16 * (64 + 8)) * 4;     // 73,728
static const int SM_AP128_3 = (4 * 3 * 16 * (128 + 8)) * 4;    // 104,448
static const int SM_FA      = 8 * FA_TSZ * 4;                  // 69,632

struct GPtrs {
    float *x, *y, *v, *tmp;
    uint32_t *encWh, *encWl, *decSWh, *decSWl, *decCWh, *decCWl;
    uint32_t *eW1h, *eW1l, *eW2h, *eW2l, *dW1h, *dW1l, *dW2h, *dW2l;
    uint32_t *oWh, *oWl;
    uint32_t *xTh, *xTl, *qkTh, *qkTl, *vPh, *vPl, *oTh, *oTl, *xeTh, *xeTl, *fTh, *fTl;
};

static void run_mha(GPtrs& G, const float* xq, const uint32_t* xkvTh, const uint32_t* xkvTl,
                    const uint32_t* wh, const uint32_t* wl, float* out, bool causal, bool self)
{
    convAT<<<dim3(TOK/32, Dd/32), 256>>>(xq, G.xTh, G.xTl, TOK, Dd);
    if (self) {
        dim3 g(TOK/64, Dd/64, 2);
        gemm_ap<64,64,128,2,4,1><<<g, 128, SM_AP64_4>>>(G.xTh, G.xTl, wh, wl,
            nullptr, nullptr, G.qkTh, G.qkTl,
            Dd, TOK, Dd, TOK,
            0, 0, 0, DD2, 0, KVC, 2, 1.0f, 0, 0);
        dim3 gv(TOK/64, Dd/64, 1);
        gemm_ap<64,64,128,2,4,0><<<gv, 128, SM_AP64_4>>>(G.xTh, G.xTl, wh + 2*DD2, wl + 2*DD2,
            nullptr, G.v, nullptr, nullptr,
            Dd, TOK, Dd, Dd,
            0, 0, 0, 0, 0, 0, 1, 1.0f, 0, 0);
    } else {
        dim3 g1(TOK/64, Dd/64, 1);
        gemm_ap<64,64,128,2,4,1><<<g1, 128, SM_AP64_4>>>(G.xTh, G.xTl, wh, wl,
            nullptr, nullptr, G.qkTh, G.qkTl,
            Dd, TOK, Dd, TOK,
            0, 0, 0, 0, 0, 0, 1, 1.0f, 0, 0);
        gemm_ap<64,64,128,2,4,1><<<g1, 128, SM_AP64_4>>>(xkvTh, xkvTl, wh + DD2, wl + DD2,
            nullptr, nullptr, G.qkTh + KVC, G.qkTl + KVC,
            Dd, TOK, Dd, TOK,
            0, 0, 0, 0, 0, 0, 1, 1.0f, 0, 0);
        gemm_ap<64,64,128,2,4,0><<<g1, 128, SM_AP64_4>>>(xkvTh, xkvTl, wh + 2*DD2, wl + 2*DD2,
            nullptr, G.v, nullptr, nullptr,
            Dd, TOK, Dd, Dd,
            0, 0, 0, 0, 0, 0, 1, 1.0f, 0, 0);
    }
    convB<<<dim3(Dd/256, TOK/2), 256>>>(G.v, G.vPh, G.vPl, Dd);

    flash_attn<<<dim3(Ss/64, Bn*Hh), 128, SM_FA>>>(
        G.qkTh, G.qkTl, G.qkTh + KVC, G.qkTl + KVC,
        G.vPh, G.vPl, G.oTh, G.oTl, causal ? 1 : 0);

    dim3 go(TOK/64, Dd/64, 1);
    gemm_ap<64,64,128,2,4,0><<<go, 128, SM_AP64_4>>>(G.oTh, G.oTl, wh + 3*DD2, wl + 3*DD2,
        nullptr, out, nullptr, nullptr,
        Dd, TOK, Dd, Dd,
        0, 0, 0, 0, 0, 0, 1, 1.0f, 0, 0);
}

static void run_ffn(GPtrs& G, float* xact, const uint32_t* w1h, const uint32_t* w1l,
                    const float* b1, const uint32_t* w2h, const uint32_t* w2l, const float* b2)
{
    convAT<<<dim3(TOK/32, Dd/32), 256>>>(xact, G.xTh, G.xTl, TOK, Dd);
    {
        dim3 g(TOK/128, FFf/128, 1);
        gemm_ap<128,128,256,4,3,1><<<g, 256, SM_AP128_3>>>(G.xTh, G.xTl, w1h, w1l,
            b1, nullptr, G.fTh, G.fTl,
            Dd, TOK, FFf, TOK,
            0, 0, 0, 0, 0, 0, 1, 1.0f, 1, 1);
    }
    {
        dim3 g(TOK/64, Dd/64, 1);
        gemm_ap<64,64,128,2,4,0><<<g, 128, SM_AP64_4>>>(G.fTh, G.fTl, w2h, w2l,
            b2, G.tmp, nullptr, nullptr,
            FFf, TOK, Dd, Dd,
            0, 0, 0, 0, 0, 0, 1, 1.0f, 1, 0);
    }
}

extern "C" void kernel_launch(void* const* d_in, const int* in_sizes, int n_in,
                              void* d_out, int out_size)
{
    const int*   src           = (const int*)  d_in[0];
    const int*   trg           = (const int*)  d_in[1];
    const float* src_emb       = (const float*)d_in[2];
    const float* trg_emb       = (const float*)d_in[3];
    const float* enc_qkvo      = (const float*)d_in[4];
    const float* enc_ffn_w1    = (const float*)d_in[5];
    const float* enc_ffn_b1    = (const float*)d_in[6];
    const float* enc_ffn_w2    = (const float*)d_in[7];
    const float* enc_ffn_b2    = (const float*)d_in[8];
    const float* dec_self_qkvo = (const float*)d_in[9];
    const float* dec_cross_qkvo= (const float*)d_in[10];
    const float* dec_ffn_w1    = (const float*)d_in[11];
    const float* dec_ffn_b1    = (const float*)d_in[12];
    const float* dec_ffn_w2    = (const float*)d_in[13];
    const float* dec_ffn_b2    = (const float*)d_in[14];
    const float* out_w         = (const float*)d_in[15];
    const float* out_b         = (const float*)d_in[16];
    float* out = (float*)d_out;

    cudaFuncSetAttribute(gemm_ap<64,64,128,2,4,0>,
                         cudaFuncAttributeMaxDynamicSharedMemorySize, SM_AP64_4);
    cudaFuncSetAttribute(gemm_ap<64,64,128,2,4,1>,
                         cudaFuncAttributeMaxDynamicSharedMemorySize, SM_AP64_4);
    cudaFuncSetAttribute(gemm_ap<128,128,256,4,3,0>,
                         cudaFuncAttributeMaxDynamicSharedMemorySize, SM_AP128_3);
    cudaFuncSetAttribute(gemm_ap<128,128,256,4,3,1>,
                         cudaFuncAttributeMaxDynamicSharedMemorySize, SM_AP128_3);
    cudaFuncSetAttribute(flash_attn,
                         cudaFuncAttributeMaxDynamicSharedMemorySize, SM_FA);

    GPtrs G;
    cudaGetSymbolAddress((void**)&G.x,    g_x);
    cudaGetSymbolAddress((void**)&G.y,    g_y);
    cudaGetSymbolAddress((void**)&G.v,    g_v);
    cudaGetSymbolAddress((void**)&G.tmp,  g_tmp);
    cudaGetSymbolAddress((void**)&G.encWh,  g_encW_h);  cudaGetSymbolAddress((void**)&G.encWl, g_encW_l);
    cudaGetSymbolAddress((void**)&G.decSWh, g_decSW_h); cudaGetSymbolAddress((void**)&G.decSWl, g_decSW_l);
    cudaGetSymbolAddress((void**)&G.decCWh, g_decCW_h); cudaGetSymbolAddress((void**)&G.decCWl, g_decCW_l);
    cudaGetSymbolAddress((void**)&G.eW1h,   g_encW1_h); cudaGetSymbolAddress((void**)&G.eW1l, g_encW1_l);
    cudaGetSymbolAddress((void**)&G.eW2h,   g_encW2_h); cudaGetSymbolAddress((void**)&G.eW2l, g_encW2_l);
    cudaGetSymbolAddress((void**)&G.dW1h,   g_decW1_h); cudaGetSymbolAddress((void**)&G.dW1l, g_decW1_l);
    cudaGetSymbolAddress((void**)&G.dW2h,   g_decW2_h); cudaGetSymbolAddress((void**)&G.dW2l, g_decW2_l);
    cudaGetSymbolAddress((void**)&G.oWh,    g_outW_h);  cudaGetSymbolAddress((void**)&G.oWl, g_outW_l);
    cudaGetSymbolAddress((void**)&G.xTh,    g_xT_h);    cudaGetSymbolAddress((void**)&G.xTl, g_xT_l);
    cudaGetSymbolAddress((void**)&G.qkTh,   g_qkT_h);   cudaGetSymbolAddress((void**)&G.qkTl, g_qkT_l);
    cudaGetSymbolAddress((void**)&G.vPh,    g_vP_h);    cudaGetSymbolAddress((void**)&G.vPl, g_vP_l);
    cudaGetSymbolAddress((void**)&G.oTh,    g_oT_h);    cudaGetSymbolAddress((void**)&G.oTl, g_oT_l);
    cudaGetSymbolAddress((void**)&G.xeTh,   g_xeT_h);   cudaGetSymbolAddress((void**)&G.xeTl, g_xeT_l);
    cudaGetSymbolAddress((void**)&G.fTh,    g_fT_h);    cudaGetSymbolAddress((void**)&G.fTl, g_fT_l);

    convB<<<dim3(Dd / 256,  24 * Dd / 2), 256>>>(enc_qkvo,       G.encWh, G.encWl, Dd);
    convB<<<dim3(Dd / 256,  24 * Dd / 2), 256>>>(dec_self_qkvo,  G.decSWh, G.decSWl, Dd);
    convB<<<dim3(Dd / 256,  24 * Dd / 2), 256>>>(dec_cross_qkvo, G.decCWh, G.decCWl, Dd);
    convB<<<dim3(FFf / 256, Nl * Dd / 2), 256>>>(enc_ffn_w1, G.eW1h, G.eW1l, FFf);
    convB<<<dim3(Dd / 256,  Nl * FFf / 2), 256>>>(enc_ffn_w2, G.eW2h, G.eW2l, Dd);
    convB<<<dim3(FFf / 256, Nl * Dd / 2), 256>>>(dec_ffn_w1, G.dW1h, G.dW1l, FFf);
    convB<<<dim3(Dd / 256,  Nl * FFf / 2), 256>>>(dec_ffn_w2, G.dW2h, G.dW2l, Dd);
    convB<<<dim3(Vv / 256,  Dd / 2), 256>>>(out_w, G.oWh, G.oWl, Vv);

    embed_pe_kernel<<<TOK, 512>>>(src, src_emb, G.x);
    embed_pe_kernel<<<TOK, 512>>>(trg, trg_emb, G.y);

    // ---------------- Encoder ----------------
    for (int i = 0; i < Nl; i++) {
        run_mha(G, G.x, nullptr, nullptr,
                G.encWh + (long long)i * 4 * DD2, G.encWl + (long long)i * 4 * DD2,
                G.tmp, false, true);
        add_ln_kernel<<<TOK, 256>>>(G.x, G.tmp);
        run_ffn(G, G.x,
                G.eW1h + (long long)i * W1SZ, G.eW1l + (long long)i * W1SZ,
                enc_ffn_b1 + (long long)i * FFf,
                G.eW2h + (long long)i * W1SZ, G.eW2l + (long long)i * W1SZ,
                enc_ffn_b2 + (long long)i * Dd);
        add_ln_kernel<<<TOK, 256>>>(G.x, G.tmp);
    }

    convAT<<<dim3(TOK/32, Dd/32), 256>>>(G.x, G.xeTh, G.xeTl, TOK, Dd);

    // ---------------- Decoder ----------------
    for (int i = 0; i < Nl; i++) {
        run_mha(G, G.y, nullptr, nullptr,
                G.decSWh + (long long)i * 4 * DD2, G.decSWl + (long long)i * 4 * DD2,
                G.tmp, true, true);
        add_ln_kernel<<<TOK, 256>>>(G.y, G.tmp);

        run_mha(G, G.y, G.xeTh, G.xeTl,
                G.decCWh + (long long)i * 4 * DD2, G.decCWl + (long long)i * 4 * DD2,
                G.tmp, false, false);
        add_ln_kernel<<<TOK, 256>>>(G.y, G.tmp);

        run_ffn(G, G.y,
                G.dW1h + (long long)i * W1SZ, G.dW1l + (long long)i * W1SZ,
                dec_ffn_b1 + (long long)i * FFf,
                G.dW2h + (long long)i * W1SZ, G.dW2l + (long long)i * W1SZ,
                dec_ffn_b2 + (long long)i * Dd);
        add_ln_kernel<<<TOK, 256>>>(G.y, G.tmp);
    }

    // ---------------- Output projection + vocab softmax ----------------
    convAT<<<dim3(TOK/32, Dd/32), 256>>>(G.y, G.xTh, G.xTl, TOK, Dd);
    {
        dim3 g(TOK/128, Vv/128, 1);
        gemm_ap<128,128,256,4,3,0><<<g, 256, SM_AP128_3>>>(G.xTh, G.xTl, G.oWh, G.oWl,
            out_b, out, nullptr, nullptr,
            Dd, TOK, Vv, Vv,
            0, 0, 0, 0, 0, 0, 1, 1.0f, 1, 0);
    }
    softmax_vocab<<<TOK, 1024>>>(out);
}

// round 10
// speedup vs baseline: 2.9636x; 1.0418x over previous
#include <cuda_runtime.h>
#include <cuda_bf16.h>
#include <math.h>
#include <stdint.h>

#define Bn   4
#define Ss   512
#define Dd   512
#define Hh   8
#define DKk  64
#define Nl   6
#define Vv   32000
#define FFf  2048
#define TOK  (Bn*Ss)

// ---------------- fp32 scratch ----------------
__device__ __align__(16) float g_x[TOK*Dd];
__device__ __align__(16) float g_y[TOK*Dd];
__device__ __align__(16) float g_tmp[TOK*Dd];

// ---------------- packed bf16x2 hi/lo ----------------
#define DD2  (Dd*Dd/2)
__device__ __align__(16) uint32_t g_encW_h[24*DD2], g_encW_l[24*DD2];
__device__ __align__(16) uint32_t g_decSW_h[24*DD2], g_decSW_l[24*DD2];
__device__ __align__(16) uint32_t g_decCW_h[24*DD2], g_decCW_l[24*DD2];
#define W1SZ (Dd*FFf/2)
__device__ __align__(16) uint32_t g_encW1_h[Nl*W1SZ], g_encW1_l[Nl*W1SZ];
__device__ __align__(16) uint32_t g_encW2_h[Nl*W1SZ], g_encW2_l[Nl*W1SZ];
__device__ __align__(16) uint32_t g_decW1_h[Nl*W1SZ], g_decW1_l[Nl*W1SZ];
__device__ __align__(16) uint32_t g_decW2_h[Nl*W1SZ], g_decW2_l[Nl*W1SZ];
#define OWSZ (Dd*Vv/2)
__device__ __align__(16) uint32_t g_outW_h[OWSZ], g_outW_l[OWSZ];
#define KVC  (TOK*Dd/2)
__device__ __align__(16) uint32_t g_xT_h[KVC],  g_xT_l[KVC];        // activation^T packed
__device__ __align__(16) uint32_t g_qkvP_h[3*KVC], g_qkvP_l[3*KVC]; // q^T | k^T | vP
__device__ __align__(16) uint32_t g_oT_h[KVC],  g_oT_l[KVC];        // attn out^T packed
__device__ __align__(16) uint32_t g_xeT_h[KVC], g_xeT_l[KVC];       // encoder out^T packed
__device__ __align__(16) uint32_t g_xKV_h[12*KVC], g_xKV_l[12*KVC]; // cross K^T|V pairs, 6 layers
#define FTSZ ((FFf/2)*TOK)
__device__ __align__(16) uint32_t g_fT_h[FTSZ], g_fT_l[FTSZ];       // ffn hidden^T packed

// ---------------- helpers ----------------
__device__ __forceinline__ void cvt_pair(float x0, float x1, uint32_t& hi, uint32_t& lo)
{
    uint32_t h;
    asm("cvt.rn.bf16x2.f32 %0, %1, %2;" : "=r"(h) : "f"(x1), "f"(x0));
    __nv_bfloat162 hb = *reinterpret_cast<__nv_bfloat162*>(&h);
    float r0 = x0 - __bfloat162float(hb.x);
    float r1 = x1 - __bfloat162float(hb.y);
    uint32_t l;
    asm("cvt.rn.bf16x2.f32 %0, %1, %2;" : "=r"(l) : "f"(r1), "f"(r0));
    hi = h; lo = l;
}

__device__ __forceinline__ uint32_t mulbf2(uint32_t a, uint32_t b)
{
    uint32_t d; asm("mul.rn.bf16x2 %0,%1,%2;" : "=r"(d) : "r"(a), "r"(b)); return d;
}

__device__ __forceinline__ void mma16816(float* c, const uint32_t* a, const uint32_t* b)
{
    asm volatile(
        "mma.sync.aligned.m16n8k16.row.col.f32.bf16.bf16.f32 "
        "{%0,%1,%2,%3}, {%4,%5,%6,%7}, {%8,%9}, {%0,%1,%2,%3};\n"
        : "+f"(c[0]), "+f"(c[1]), "+f"(c[2]), "+f"(c[3])
        : "r"(a[0]), "r"(a[1]), "r"(a[2]), "r"(a[3]), "r"(b[0]), "r"(b[1]));
}

__device__ __forceinline__ void cp_async16(uint32_t s, const void* g)
{
    asm volatile("cp.async.cg.shared.global [%0], [%1], 16;" :: "r"(s), "l"(g));
}
#define CP_COMMIT() asm volatile("cp.async.commit_group;")

__device__ __forceinline__ void cp_wait_n(int n)
{
    switch (n) {
    case 0: asm volatile("cp.async.wait_group 0;"); break;
    case 1: asm volatile("cp.async.wait_group 1;"); break;
    case 2: asm volatile("cp.async.wait_group 2;"); break;
    default: asm volatile("cp.async.wait_group 3;"); break;
    }
}

// ---------------- conversion kernels ----------------
__global__ __launch_bounds__(256)
void convB(const float* __restrict__ W, uint32_t* __restrict__ H,
           uint32_t* __restrict__ L, int C)
{
    long long kp = blockIdx.y;
    int c = blockIdx.x * 256 + threadIdx.x;
    float a = W[(2*kp) * (long long)C + c];
    float b = W[(2*kp+1) * (long long)C + c];
    uint32_t h, l; cvt_pair(a, b, h, l);
    long long o = kp * C + c;
    H[o] = h; L[o] = l;
}

__global__ __launch_bounds__(256)
void convAT(const float* __restrict__ X, uint32_t* __restrict__ H,
            uint32_t* __restrict__ L, int Mdim, int Kdim)
{
    __shared__ float s[32][33];
    int m0 = blockIdx.x * 32, k0 = blockIdx.y * 32;
    int tx = threadIdx.x & 31, ty = threadIdx.x >> 5;
#pragma unroll
    for (int i = 0; i < 4; i++) {
        int m = ty + i * 8;
        s[m][tx] = X[(long long)(m0 + m) * Kdim + k0 + tx];
    }
    __syncthreads();
    int om = threadIdx.x & 31, okp = threadIdx.x >> 5;
#pragma unroll
    for (int i = 0; i < 2; i++) {
        int kp = okp + i * 8;
        uint32_t h, l;
        cvt_pair(s[om][2*kp], s[om][2*kp+1], h, l);
        long long o = (long long)(k0/2 + kp) * Mdim + m0 + om;
        H[o] = h; L[o] = l;
    }
}

// ---------------- all-packed GEMM ----------------
// PACKMODE 0: C fp32 row-major
// PACKMODE 1: bf16x2 hi/lo transposed-packed [N/2][ldc]   (pairs along N)
// PACKMODE 3: per-z: zi < rThresh -> mode 1; zi >= rThresh -> mode 2
//   mode 2 (PACKR): bf16x2 hi/lo row-pair packed [M/2][ldc2] (pairs along M)
template<int TBM, int TBN, int NTHREADS, int WARPS_M, int STAGES, int PACKMODE>
__global__ __launch_bounds__(NTHREADS)
void gemm_ap(const uint32_t* __restrict__ AH, const uint32_t* __restrict__ AL,
             const uint32_t* __restrict__ BH, const uint32_t* __restrict__ BL,
             const float* __restrict__ bias, float* __restrict__ C,
             uint32_t* __restrict__ CH, uint32_t* __restrict__ CL,
             int K, int ldap, int ldbp, int ldc, int ldc2,
             long long sAo, long long sAi, long long sBo, long long sBi,
             long long sCo, long long sCi, int Hsub, int rThresh,
             float alpha, int doBias, int doRelu)
{
    constexpr int WARPS   = NTHREADS / 32;
    constexpr int WARPS_N = WARPS / WARPS_M;
    constexpr int WM = TBM / WARPS_M;
    constexpr int WN = TBN / WARPS_N;
    constexpr int MT = WM / 16;
    constexpr int NT = WN / 8;
    constexpr int AS = TBM + 8;
    constexpr int BS = TBN + 8;
    constexpr int ASZ = 16 * AS;
    constexpr int BSZ = 16 * BS;
    constexpr int AC = (16 * (TBM / 4)) / NTHREADS;
    constexpr int BC = (16 * (TBN / 4)) / NTHREADS;

    extern __shared__ uint32_t smem[];
    uint32_t* sAh = smem;
    uint32_t* sAl = smem + STAGES * ASZ;
    uint32_t* sBh = smem + 2 * STAGES * ASZ;
    uint32_t* sBl = smem + 2 * STAGES * ASZ + STAGES * BSZ;

    int z = blockIdx.z;
    int zo = z / Hsub, zi = z % Hsub;
    const uint32_t* Ahb = AH + zo * sAo + zi * sAi;
    const uint32_t* Alb = AL + zo * sAo + zi * sAi;
    const uint32_t* Bhb = BH + zo * sBo + zi * sBi;
    const uint32_t* Blb = BL + zo * sBo + zi * sBi;
    float*    Cb  = (PACKMODE == 0) ? (C + zo * sCo + zi * sCi) : nullptr;
    uint32_t* CHb = (PACKMODE != 0) ? (CH + zo * sCo + zi * sCi) : nullptr;
    uint32_t* CLb = (PACKMODE != 0) ? (CL + zo * sCo + zi * sCi) : nullptr;

    int tid = threadIdx.x;
    int wid = tid >> 5, lane = tid & 31;
    int wm = wid % WARPS_M, wn = wid / WARPS_M;
    int group = lane >> 2, tig = lane & 3;
    int row0 = blockIdx.x * TBM;
    int col0 = blockIdx.y * TBN;

    auto cpStage = [&](int k0, int st) {
        int kp0 = k0 >> 1;
        uint32_t ah0 = (uint32_t)__cvta_generic_to_shared(sAh + st * ASZ);
        uint32_t al0 = (uint32_t)__cvta_generic_to_shared(sAl + st * ASZ);
#pragma unroll
        for (int j = 0; j < AC; j++) {
            int ci = tid + j * NTHREADS;
            int rr = ci / (TBM / 4), cc = ci % (TBM / 4);
            long long go = (long long)(kp0 + rr) * ldap + row0 + cc * 4;
            uint32_t so = (rr * AS + cc * 4) * 4;
            cp_async16(ah0 + so, Ahb + go);
            cp_async16(al0 + so, Alb + go);
        }
        uint32_t bh0 = (uint32_t)__cvta_generic_to_shared(sBh + st * BSZ);
        uint32_t bl0 = (uint32_t)__cvta_generic_to_shared(sBl + st * BSZ);
#pragma unroll
        for (int j = 0; j < BC; j++) {
            int ci = tid + j * NTHREADS;
            int rr = ci / (TBN / 4), cc = ci % (TBN / 4);
            long long go = (long long)(kp0 + rr) * ldbp + col0 + cc * 4;
            uint32_t so = (rr * BS + cc * 4) * 4;
            cp_async16(bh0 + so, Bhb + go);
            cp_async16(bl0 + so, Blb + go);
        }
        CP_COMMIT();
    };

    float acc[MT][NT][4];
#pragma unroll
    for (int i = 0; i < MT; i++)
#pragma unroll
        for (int j = 0; j < NT; j++)
#pragma unroll
            for (int t = 0; t < 4; t++) acc[i][j][t] = 0.f;

    int kpref = 0;
#pragma unroll
    for (int s = 0; s < STAGES - 1; s++) { cpStage(kpref, s); kpref += 32; }

    int st = 0;
    for (int k0 = 0; k0 < K; k0 += 32) {
        if (kpref < K) {
            cpStage(kpref, (kpref >> 5) % STAGES);
            kpref += 32;
        }
        cp_wait_n(((kpref - k0) >> 5) - 1);
        __syncthreads();

        const uint32_t* Ahs = sAh + st * ASZ;
        const uint32_t* Als = sAl + st * ASZ;
        const uint32_t* Bhs = sBh + st * BSZ;
        const uint32_t* Bls = sBl + st * BSZ;
#pragma unroll
        for (int ks = 0; ks < 2; ks++) {
            uint32_t ah[MT][4], al[MT][4], bh[NT][2], bl[NT][2];
            int kp0 = ks * 8 + tig, kp1 = kp0 + 4;
#pragma unroll
            for (int mt = 0; mt < MT; mt++) {
                int r = wm * WM + mt * 16 + group;
                ah[mt][0] = Ahs[kp0 * AS + r];     al[mt][0] = Als[kp0 * AS + r];
                ah[mt][1] = Ahs[kp0 * AS + r + 8]; al[mt][1] = Als[kp0 * AS + r + 8];
                ah[mt][2] = Ahs[kp1 * AS + r];     al[mt][2] = Als[kp1 * AS + r];
                ah[mt][3] = Ahs[kp1 * AS + r + 8]; al[mt][3] = Als[kp1 * AS + r + 8];
            }
#pragma unroll
            for (int nt = 0; nt < NT; nt++) {
                int c = wn * WN + nt * 8 + group;
                bh[nt][0] = Bhs[kp0 * BS + c];  bl[nt][0] = Bls[kp0 * BS + c];
                bh[nt][1] = Bhs[kp1 * BS + c];  bl[nt][1] = Bls[kp1 * BS + c];
            }
            // term-major: MT*NT independent mmas between accumulator reuse
#pragma unroll
            for (int mt = 0; mt < MT; mt++)
#pragma unroll
                for (int nt = 0; nt < NT; nt++)
                    mma16816(acc[mt][nt], ah[mt], bh[nt]);
#pragma unroll
            for (int mt = 0; mt < MT; mt++)
#pragma unroll
                for (int nt = 0; nt < NT; nt++)
                    mma16816(acc[mt][nt], al[mt], bh[nt]);
#pragma unroll
            for (int mt = 0; mt < MT; mt++)
#pragma unroll
                for (int nt = 0; nt < NT; nt++)
                    mma16816(acc[mt][nt], ah[mt], bl[nt]);
        }
        __syncthreads();
        if (++st == STAGES) st = 0;
    }

    int effMode = (PACKMODE == 3) ? ((zi >= rThresh) ? 2 : 1) : PACKMODE;

#pragma unroll
    for (int mt = 0; mt < MT; mt++) {
        int r = row0 + wm * WM + mt * 16 + group;
#pragma unroll
        for (int nt = 0; nt < NT; nt++) {
            int c = col0 + wn * WN + nt * 8 + tig * 2;
            float v00 = acc[mt][nt][0] * alpha;
            float v01 = acc[mt][nt][1] * alpha;
            float v10 = acc[mt][nt][2] * alpha;
            float v11 = acc[mt][nt][3] * alpha;
            if (doBias) {
                float2 bb = *reinterpret_cast<const float2*>(&bias[c]);
                v00 += bb.x; v01 += bb.y; v10 += bb.x; v11 += bb.y;
            }
            if (doRelu) {
                v00 = fmaxf(v00, 0.f); v01 = fmaxf(v01, 0.f);
                v10 = fmaxf(v10, 0.f); v11 = fmaxf(v11, 0.f);
            }
            if (PACKMODE == 0) {
                *reinterpret_cast<float2*>(&Cb[(long long)r * ldc + c])       = make_float2(v00, v01);
                *reinterpret_cast<float2*>(&Cb[(long long)(r + 8) * ldc + c]) = make_float2(v10, v11);
            } else if (effMode == 1) {
                long long base = (long long)(c >> 1) * ldc + r;
                uint32_t h, l;
                cvt_pair(v00, v01, h, l); CHb[base] = h;     CLb[base] = l;
                cvt_pair(v10, v11, h, l); CHb[base + 8] = h; CLb[base + 8] = l;
            } else {
                // PACKR: pair rows (r, r+1) via shuffle from group+1 (lane+4)
                float u00 = __shfl_down_sync(0xffffffffu, v00, 4);
                float u01 = __shfl_down_sync(0xffffffffu, v01, 4);
                float u10 = __shfl_down_sync(0xffffffffu, v10, 4);
                float u11 = __shfl_down_sync(0xffffffffu, v11, 4);
                if (!(group & 1)) {
                    long long b0 = (long long)(r >> 1) * ldc2 + c;
                    long long b8 = (long long)((r + 8) >> 1) * ldc2 + c;
                    uint32_t h, l;
                    cvt_pair(v00, u00, h, l); CHb[b0]     = h; CLb[b0]     = l;
                    cvt_pair(v01, u01, h, l); CHb[b0 + 1] = h; CLb[b0 + 1] = l;
                    cvt_pair(v10, u10, h, l); CHb[b8]     = h; CLb[b8]     = l;
                    cvt_pair(v11, u11, h, l); CHb[b8 + 1] = h; CLb[b8 + 1] = l;
                }
            }
        }
    }
}

// ---------------- fused flash attention ----------------
#define FA_STRIDE 68
#define FA_TSZ (32 * FA_STRIDE)
__global__ __launch_bounds__(128)
void flash_attn(const uint32_t* __restrict__ Qh, const uint32_t* __restrict__ Ql,
                const uint32_t* __restrict__ Kh, const uint32_t* __restrict__ Kl,
                const uint32_t* __restrict__ Vh, const uint32_t* __restrict__ Vl,
                uint32_t* __restrict__ Oh, uint32_t* __restrict__ Ol, int causal)
{
    extern __shared__ uint32_t smem[];
    uint32_t* sKh = smem;
    uint32_t* sKl = smem + 2 * FA_TSZ;
    uint32_t* sVh = smem + 4 * FA_TSZ;
    uint32_t* sVl = smem + 6 * FA_TSZ;

    int qb = blockIdx.x;
    int b  = blockIdx.y / Hh;
    int h  = blockIdx.y % Hh;
    int tid = threadIdx.x;
    int wid = tid >> 5, lane = tid & 31;
    int group = lane >> 2, tig = lane & 3;
    int tokBase = b * Ss + qb * 64 + wid * 16;

    uint32_t qh[4][4], ql[4][4];
    const uint32_t SC = 0x3E003E00u;  // bf16x2(0.125, 0.125), exact
#pragma unroll
    for (int ks = 0; ks < 4; ks++) {
        int kpa = h * 32 + ks * 8 + tig;
        long long b0 = (long long)kpa * TOK + tokBase + group;
        long long b2 = (long long)(kpa + 4) * TOK + tokBase + group;
        qh[ks][0] = mulbf2(Qh[b0], SC);     ql[ks][0] = mulbf2(Ql[b0], SC);
        qh[ks][1] = mulbf2(Qh[b0 + 8], SC); ql[ks][1] = mulbf2(Ql[b0 + 8], SC);
        qh[ks][2] = mulbf2(Qh[b2], SC);     ql[ks][2] = mulbf2(Ql[b2], SC);
        qh[ks][3] = mulbf2(Qh[b2 + 8], SC); ql[ks][3] = mulbf2(Ql[b2 + 8], SC);
    }

    float m0 = -INFINITY, m1 = -INFINITY, l0 = 0.f, l1 = 0.f;
    float acc_o[8][4];
#pragma unroll
    for (int nt = 0; nt < 8; nt++)
#pragma unroll
        for (int t = 0; t < 4; t++) acc_o[nt][t] = 0.f;

    int nkb = causal ? (qb + 1) : (Ss / 64);

    auto cpStage = [&](int kb, int stg) {
        uint32_t kh0 = (uint32_t)__cvta_generic_to_shared(sKh + stg * FA_TSZ);
        uint32_t kl0 = (uint32_t)__cvta_generic_to_shared(sKl + stg * FA_TSZ);
        uint32_t vh0 = (uint32_t)__cvta_generic_to_shared(sVh + stg * FA_TSZ);
        uint32_t vl0 = (uint32_t)__cvta_generic_to_shared(sVl + stg * FA_TSZ);
#pragma unroll
        for (int i = 0; i < 4; i++) {
            int idx = tid + i * 128;
            int row = idx >> 4, c4 = idx & 15;
            uint32_t so = (row * FA_STRIDE + c4 * 4) * 4;
            long long gK = (long long)(h * 32 + row) * TOK + b * Ss + kb * 64 + c4 * 4;
            cp_async16(kh0 + so, Kh + gK);
            cp_async16(kl0 + so, Kl + gK);
            long long gV = (long long)(b * (Ss / 2) + kb * 32 + row) * Dd + h * 64 + c4 * 4;
            cp_async16(vh0 + so, Vh + gV);
            cp_async16(vl0 + so, Vl + gV);
        }
        CP_COMMIT();
    };

    cpStage(0, 0);
    for (int kb = 0; kb < nkb; kb++) {
        if (kb + 1 < nkb) {
            cpStage(kb + 1, (kb + 1) & 1);
            asm volatile("cp.async.wait_group 1;");
        } else {
            asm volatile("cp.async.wait_group 0;");
        }
        __syncthreads();
        int stg = kb & 1;
        const uint32_t* Ksh = sKh + stg * FA_TSZ;
        const uint32_t* Ksl = sKl + stg * FA_TSZ;
        const uint32_t* Vsh = sVh + stg * FA_TSZ;
        const uint32_t* Vsl = sVl + stg * FA_TSZ;

        float s[8][4];
#pragma unroll
        for (int nt = 0; nt < 8; nt++)
#pragma unroll
            for (int t = 0; t < 4; t++) s[nt][t] = 0.f;
#pragma unroll
        for (int ks = 0; ks < 4; ks++) {
            int r0 = (ks * 8 + tig) * FA_STRIDE, r1 = r0 + 4 * FA_STRIDE;
            uint32_t bhf[8][2], blf[8][2];
#pragma unroll
            for (int nt = 0; nt < 8; nt++) {
                int c = nt * 8 + group;
                bhf[nt][0] = Ksh[r0 + c]; bhf[nt][1] = Ksh[r1 + c];
                blf[nt][0] = Ksl[r0 + c]; blf[nt][1] = Ksl[r1 + c];
            }
            // term-major
#pragma unroll
            for (int nt = 0; nt < 8; nt++) mma16816(s[nt], qh[ks], bhf[nt]);
#pragma unroll
            for (int nt = 0; nt < 8; nt++) mma16816(s[nt], ql[ks], bhf[nt]);
#pragma unroll
            for (int nt = 0; nt < 8; nt++) mma16816(s[nt], qh[ks], blf[nt]);
        }

        if (causal && kb == qb) {
            int r0 = wid * 16 + group, r1 = r0 + 8;
#pragma unroll
            for (int nt = 0; nt < 8; nt++) {
                int c0 = nt * 8 + tig * 2;
                if (c0     > r0) s[nt][0] = -1e9f;
                if (c0 + 1 > r0) s[nt][1] = -1e9f;
                if (c0     > r1) s[nt][2] = -1e9f;
                if (c0 + 1 > r1) s[nt][3] = -1e9f;
            }
        }

        float bm0 = -INFINITY, bm1 = -INFINITY;
#pragma unroll
        for (int nt = 0; nt < 8; nt++) {
            bm0 = fmaxf(bm0, fmaxf(s[nt][0], s[nt][1]));
            bm1 = fmaxf(bm1, fmaxf(s[nt][2], s[nt][3]));
        }
        bm0 = fmaxf(bm0, __shfl_xor_sync(0xffffffffu, bm0, 1));
        bm0 = fmaxf(bm0, __shfl_xor_sync(0xffffffffu, bm0, 2));
        bm1 = fmaxf(bm1, __shfl_xor_sync(0xffffffffu, bm1, 1));
        bm1 = fmaxf(bm1, __shfl_xor_sync(0xffffffffu, bm1, 2));
        float nm0 = fmaxf(m0, bm0), nm1 = fmaxf(m1, bm1);
        float a0f = __expf(m0 - nm0), a1f = __expf(m1 - nm1);
        m0 = nm0; m1 = nm1;
        float rs0 = 0.f, rs1 = 0.f;
#pragma unroll
        for (int nt = 0; nt < 8; nt++) {
            s[nt][0] = __expf(s[nt][0] - nm0);
            s[nt][1] = __expf(s[nt][1] - nm0);
            s[nt][2] = __expf(s[nt][2] - nm1);
            s[nt][3] = __expf(s[nt][3] - nm1);
            rs0 += s[nt][0] + s[nt][1];
            rs1 += s[nt][2] + s[nt][3];
        }
        rs0 += __shfl_xor_sync(0xffffffffu, rs0, 1);
        rs0 += __shfl_xor_sync(0xffffffffu, rs0, 2);
        rs1 += __shfl_xor_sync(0xffffffffu, rs1, 1);
        rs1 += __shfl_xor_sync(0xffffffffu, rs1, 2);
        l0 = l0 * a0f + rs0;
        l1 = l1 * a1f + rs1;
#pragma unroll
        for (int nt = 0; nt < 8; nt++) {
            acc_o[nt][0] *= a0f; acc_o[nt][1] *= a0f;
            acc_o[nt][2] *= a1f; acc_o[nt][3] *= a1f;
        }

        uint32_t ph[4][4], pl[4][4];
#pragma unroll
        for (int j = 0; j < 4; j++) {
            cvt_pair(s[2*j  ][0], s[2*j  ][1], ph[j][0], pl[j][0]);
            cvt_pair(s[2*j  ][2], s[2*j  ][3], ph[j][1], pl[j][1]);
            cvt_pair(s[2*j+1][0], s[2*j+1][1], ph[j][2], pl[j][2]);
            cvt_pair(s[2*j+1][2], s[2*j+1][3], ph[j][3], pl[j][3]);
        }

#pragma unroll
        for (int j = 0; j < 4; j++) {
            int r0 = (j * 8 + tig) * FA_STRIDE, r1 = r0 + 4 * FA_STRIDE;
            uint32_t vbh[8][2], vbl[8][2];
#pragma unroll
            for (int nt = 0; nt < 8; nt++) {
                int c = nt * 8 + group;
                vbh[nt][0] = Vsh[r0 + c]; vbh[nt][1] = Vsh[r1 + c];
                vbl[nt][0] = Vsl[r0 + c]; vbl[nt][1] = Vsl[r1 + c];
            }
            // term-major
#pragma unroll
            for (int nt = 0; nt < 8; nt++) mma16816(acc_o[nt], ph[j], vbh[nt]);
#pragma unroll
            for (int nt = 0; nt < 8; nt++) mma16816(acc_o[nt], pl[j], vbh[nt]);
#pragma unroll
            for (int nt = 0; nt < 8; nt++) mma16816(acc_o[nt], ph[j], vbl[nt]);
        }
        __syncthreads();
    }

    float inv0 = 1.0f / l0, inv1 = 1.0f / l1;
#pragma unroll
    for (int nt = 0; nt < 8; nt++) {
        int cp = h * 32 + nt * 4 + tig;
        long long bo = (long long)cp * TOK + tokBase + group;
        uint32_t hh, ll;
        cvt_pair(acc_o[nt][0] * inv0, acc_o[nt][1] * inv0, hh, ll);
        Oh[bo] = hh; Ol[bo] = ll;
        cvt_pair(acc_o[nt][2] * inv1, acc_o[nt][3] * inv1, hh, ll);
        Oh[bo + 8] = hh; Ol[bo + 8] = ll;
    }
}

// ---------------- vocab softmax ----------
__global__ __launch_bounds__(1024)
void softmax_vocab(float* __restrict__ P)
{
    float* p = P + (long long)blockIdx.x * Vv;
    int t = threadIdx.x;
    __shared__ float red[32];
    float v[32];
    float mx = -3.0e38f;
#pragma unroll
    for (int i = 0; i < 32; i++) {
        int idx = t + i * 1024;
        v[i] = (idx < Vv) ? p[idx] : -3.0e38f;
        mx = fmaxf(mx, v[i]);
    }
    for (int o = 16; o; o >>= 1) mx = fmaxf(mx, __shfl_xor_sync(0xffffffffu, mx, o));
    if ((t & 31) == 0) red[t >> 5] = mx;
    __syncthreads();
    if (t < 32) {
        float m2 = red[t];
        for (int o = 16; o; o >>= 1) m2 = fmaxf(m2, __shfl_xor_sync(0xffffffffu, m2, o));
        if (t == 0) red[0] = m2;
    }
    __syncthreads();
    mx = red[0];
    __syncthreads();
    float sum = 0.f;
#pragma unroll
    for (int i = 0; i < 32; i++) { v[i] = __expf(v[i] - mx); sum += v[i]; }
    for (int o = 16; o; o >>= 1) sum += __shfl_xor_sync(0xffffffffu, sum, o);
    if ((t & 31) == 0) red[t >> 5] = sum;
    __syncthreads();
    if (t < 32) {
        float s2 = red[t];
        for (int o = 16; o; o >>= 1) s2 += __shfl_xor_sync(0xffffffffu, s2, o);
        if (t == 0) red[0] = s2;
    }
    __syncthreads();
    float inv = 1.0f / red[0];
#pragma unroll
    for (int i = 0; i < 32; i++) {
        int idx = t + i * 1024;
        if (idx < Vv) p[idx] = v[i] * inv;
    }
}

// ---------------- add + LayerNorm ----------
__global__ __launch_bounds__(256)
void add_ln_kernel(float* __restrict__ x, const float* __restrict__ sub)
{
    int row = blockIdx.x;
    float* xr = x + (long long)row * Dd;
    const float* sr = sub + (long long)row * Dd;
    int t = threadIdx.x;
    __shared__ float red[256];

    float v0 = xr[t] + sr[t];
    float v1 = xr[t + 256] + sr[t + 256];
    red[t] = v0 + v1; __syncthreads();
    for (int o = 128; o; o >>= 1) { if (t < o) red[t] += red[t + o]; __syncthreads(); }
    float mu = red[0] * (1.0f / 512.0f); __syncthreads();
    float d0 = v0 - mu, d1 = v1 - mu;
    red[t] = d0 * d0 + d1 * d1; __syncthreads();
    for (int o = 128; o; o >>= 1) { if (t < o) red[t] += red[t + o]; __syncthreads(); }
    float inv = rsqrtf(red[0] * (1.0f / 512.0f) + 1e-5f);
    xr[t] = d0 * inv;
    xr[t + 256] = d1 * inv;
}

// ---------------- embedding + PE ----------
__global__ __launch_bounds__(512)
void embed_pe_kernel(const int* __restrict__ tok, const float* __restrict__ emb,
                     float* __restrict__ out)
{
    int idx = blockIdx.x;
    int s = idx % Ss;
    int j = threadIdx.x;
    int tk = tok[idx];
    float ang = (float)s * powf(10000.0f, -2.0f * (float)j / 512.0f);
    float pe = (j & 1) ? cosf(ang) : sinf(ang);
    out[(long long)idx * Dd + j] = emb[(long long)tk * Dd + j] + pe;
}

// ---------------- host ----------------
static const int SM_AP64_3  = (4 * 3 * 16 * (64 + 8)) * 4;     // 55,296
static const int SM_AP128_3 = (4 * 3 * 16 * (128 + 8)) * 4;    // 104,448
static const int SM_FA      = 8 * FA_TSZ * 4;                  // 69,632

struct GPtrs {
    float *x, *y, *tmp;
    uint32_t *encWh, *encWl, *decSWh, *decSWl, *decCWh, *decCWl;
    uint32_t *eW1h, *eW1l, *eW2h, *eW2l, *dW1h, *dW1l, *dW2h, *dW2l;
    uint32_t *oWh, *oWl;
    uint32_t *xTh, *xTl, *qkvPh, *qkvPl, *oTh, *oTl, *xeTh, *xeTl, *xKVh, *xKVl, *fTh, *fTl;
};

static void run_mha_self(GPtrs& G, const float* xq,
                         const uint32_t* wh, const uint32_t* wl, float* out, bool causal)
{
    convAT<<<dim3(TOK/32, Dd/32), 256>>>(xq, G.xTh, G.xTl, TOK, Dd);
    // q,k,v in one z=3 launch: z<2 -> PACKT (q^T, k^T), z==2 -> PACKR (vP)
    {
        dim3 g(TOK/64, Dd/64, 3);
        gemm_ap<64,64,128,2,3,3><<<g, 128, SM_AP64_3>>>(G.xTh, G.xTl, wh, wl,
            nullptr, nullptr, G.qkvPh, G.qkvPl,
            Dd, TOK, Dd, TOK, Dd,
            0, 0, 0, DD2, 0, KVC, 3, 2, 1.0f, 0, 0);
    }
    flash_attn<<<dim3(Ss/64, Bn*Hh), 128, SM_FA>>>(
        G.qkvPh, G.qkvPl, G.qkvPh + KVC, G.qkvPl + KVC,
        G.qkvPh + 2*KVC, G.qkvPl + 2*KVC, G.oTh, G.oTl, causal ? 1 : 0);
    {
        dim3 g(TOK/64, Dd/64, 1);
        gemm_ap<64,64,128,2,3,0><<<g, 128, SM_AP64_3>>>(G.oTh, G.oTl, wh + 3*DD2, wl + 3*DD2,
            nullptr, out, nullptr, nullptr,
            Dd, TOK, Dd, Dd, Dd,
            0, 0, 0, 0, 0, 0, 1, 0, 1.0f, 0, 0);
    }
}

static void run_mha_cross(GPtrs& G, const float* yq, int layer,
                          const uint32_t* wh, const uint32_t* wl, float* out)
{
    convAT<<<dim3(TOK/32, Dd/32), 256>>>(yq, G.xTh, G.xTl, TOK, Dd);
    {
        dim3 g(TOK/64, Dd/64, 1);
        gemm_ap<64,64,128,2,3,1><<<g, 128, SM_AP64_3>>>(G.xTh, G.xTl, wh, wl,
            nullptr, nullptr, G.qkvPh, G.qkvPl,
            Dd, TOK, Dd, TOK, Dd,
            0, 0, 0, 0, 0, 0, 1, 0, 1.0f, 0, 0);
    }
    const uint32_t* kh = G.xKVh + (long long)layer * 2 * KVC;
    const uint32_t* kl = G.xKVl + (long long)layer * 2 * KVC;
    flash_attn<<<dim3(Ss/64, Bn*Hh), 128, SM_FA>>>(
        G.qkvPh, G.qkvPl, kh, kl, kh + KVC, kl + KVC, G.oTh, G.oTl, 0);
    {
        dim3 g(TOK/64, Dd/64, 1);
        gemm_ap<64,64,128,2,3,0><<<g, 128, SM_AP64_3>>>(G.oTh, G.oTl, wh + 3*DD2, wl + 3*DD2,
            nullptr, out, nullptr, nullptr,
            Dd, TOK, Dd, Dd, Dd,
            0, 0, 0, 0, 0, 0, 1, 0, 1.0f, 0, 0);
    }
}

static void run_ffn(GPtrs& G, float* xact, const uint32_t* w1h, const uint32_t* w1l,
                    const float* b1, const uint32_t* w2h, const uint32_t* w2l, const float* b2)
{
    convAT<<<dim3(TOK/32, Dd/32), 256>>>(xact, G.xTh, G.xTl, TOK, Dd);
    {
        dim3 g(TOK/128, FFf/128, 1);
        gemm_ap<128,128,256,4,3,1><<<g, 256, SM_AP128_3>>>(G.xTh, G.xTl, w1h, w1l,
            b1, nullptr, G.fTh, G.fTl,
            Dd, TOK, FFf, TOK, Dd,
            0, 0, 0, 0, 0, 0, 1, 0, 1.0f, 1, 1);
    }
    {
        dim3 g(TOK/64, Dd/64, 1);
        gemm_ap<64,64,128,2,3,0><<<g, 128, SM_AP64_3>>>(G.fTh, G.fTl, w2h, w2l,
            b2, G.tmp, nullptr, nullptr,
            FFf, TOK, Dd, Dd, Dd,
            0, 0, 0, 0, 0, 0, 1, 0, 1.0f, 1, 0);
    }
}

extern "C" void kernel_launch(void* const* d_in, const int* in_sizes, int n_in,
                              void* d_out, int out_size)
{
    const int*   src           = (const int*)  d_in[0];
    const int*   trg           = (const int*)  d_in[1];
    const float* src_emb       = (const float*)d_in[2];
    const float* trg_emb       = (const float*)d_in[3];
    const float* enc_qkvo      = (const float*)d_in[4];
    const float* enc_ffn_w1    = (const float*)d_in[5];
    const float* enc_ffn_b1    = (const float*)d_in[6];
    const float* enc_ffn_w2    = (const float*)d_in[7];
    const float* enc_ffn_b2    = (const float*)d_in[8];
    const float* dec_self_qkvo = (const float*)d_in[9];
    const float* dec_cross_qkvo= (const float*)d_in[10];
    const float* dec_ffn_w1    = (const float*)d_in[11];
    const float* dec_ffn_b1    = (const float*)d_in[12];
    const float* dec_ffn_w2    = (const float*)d_in[13];
    const float* dec_ffn_b2    = (const float*)d_in[14];
    const float* out_w         = (const float*)d_in[15];
    const float* out_b         = (const float*)d_in[16];
    float* out = (float*)d_out;

    cudaFuncSetAttribute(gemm_ap<64,64,128,2,3,0>,
                         cudaFuncAttributeMaxDynamicSharedMemorySize, SM_AP64_3);
    cudaFuncSetAttribute(gemm_ap<64,64,128,2,3,1>,
                         cudaFuncAttributeMaxDynamicSharedMemorySize, SM_AP64_3);
    cudaFuncSetAttribute(gemm_ap<64,64,128,2,3,3>,
                         cudaFuncAttributeMaxDynamicSharedMemorySize, SM_AP64_3);
    cudaFuncSetAttribute(gemm_ap<128,128,256,4,3,0>,
                         cudaFuncAttributeMaxDynamicSharedMemorySize, SM_AP128_3);
    cudaFuncSetAttribute(gemm_ap<128,128,256,4,3,1>,
                         cudaFuncAttributeMaxDynamicSharedMemorySize, SM_AP128_3);
    cudaFuncSetAttribute(flash_attn,
                         cudaFuncAttributeMaxDynamicSharedMemorySize, SM_FA);

    GPtrs G;
    cudaGetSymbolAddress((void**)&G.x,    g_x);
    cudaGetSymbolAddress((void**)&G.y,    g_y);
    cudaGetSymbolAddress((void**)&G.tmp,  g_tmp);
    cudaGetSymbolAddress((void**)&G.encWh,  g_encW_h);  cudaGetSymbolAddress((void**)&G.encWl, g_encW_l);
    cudaGetSymbolAddress((void**)&G.decSWh, g_decSW_h); cudaGetSymbolAddress((void**)&G.decSWl, g_decSW_l);
    cudaGetSymbolAddress((void**)&G.decCWh, g_decCW_h); cudaGetSymbolAddress((void**)&G.decCWl, g_decCW_l);
    cudaGetSymbolAddress((void**)&G.eW1h,   g_encW1_h); cudaGetSymbolAddress((void**)&G.eW1l, g_encW1_l);
    cudaGetSymbolAddress((void**)&G.eW2h,   g_encW2_h); cudaGetSymbolAddress((void**)&G.eW2l, g_encW2_l);
    cudaGetSymbolAddress((void**)&G.dW1h,   g_decW1_h); cudaGetSymbolAddress((void**)&G.dW1l, g_decW1_l);
    cudaGetSymbolAddress((void**)&G.dW2h,   g_decW2_h); cudaGetSymbolAddress((void**)&G.dW2l, g_decW2_l);
    cudaGetSymbolAddress((void**)&G.oWh,    g_outW_h);  cudaGetSymbolAddress((void**)&G.oWl, g_outW_l);
    cudaGetSymbolAddress((void**)&G.xTh,    g_xT_h);    cudaGetSymbolAddress((void**)&G.xTl, g_xT_l);
    cudaGetSymbolAddress((void**)&G.qkvPh,  g_qkvP_h);  cudaGetSymbolAddress((void**)&G.qkvPl, g_qkvP_l);
    cudaGetSymbolAddress((void**)&G.oTh,    g_oT_h);    cudaGetSymbolAddress((void**)&G.oTl, g_oT_l);
    cudaGetSymbolAddress((void**)&G.xeTh,   g_xeT_h);   cudaGetSymbolAddress((void**)&G.xeTl, g_xeT_l);
    cudaGetSymbolAddress((void**)&G.xKVh,   g_xKV_h);   cudaGetSymbolAddress((void**)&G.xKVl, g_xKV_l);
    cudaGetSymbolAddress((void**)&G.fTh,    g_fT_h);    cudaGetSymbolAddress((void**)&G.fTl, g_fT_l);

    convB<<<dim3(Dd / 256,  24 * Dd / 2), 256>>>(enc_qkvo,       G.encWh, G.encWl, Dd);
    convB<<<dim3(Dd / 256,  24 * Dd / 2), 256>>>(dec_self_qkvo,  G.decSWh, G.decSWl, Dd);
    convB<<<dim3(Dd / 256,  24 * Dd / 2), 256>>>(dec_cross_qkvo, G.decCWh, G.decCWl, Dd);
    convB<<<dim3(FFf / 256, Nl * Dd / 2), 256>>>(enc_ffn_w1, G.eW1h, G.eW1l, FFf);
    convB<<<dim3(Dd / 256,  Nl * FFf / 2), 256>>>(enc_ffn_w2, G.eW2h, G.eW2l, Dd);
    convB<<<dim3(FFf / 256, Nl * Dd / 2), 256>>>(dec_ffn_w1, G.dW1h, G.dW1l, FFf);
    convB<<<dim3(Dd / 256,  Nl * FFf / 2), 256>>>(dec_ffn_w2, G.dW2h, G.dW2l, Dd);
    convB<<<dim3(Vv / 256,  Dd / 2), 256>>>(out_w, G.oWh, G.oWl, Vv);

    embed_pe_kernel<<<TOK, 512>>>(src, src_emb, G.x);
    embed_pe_kernel<<<TOK, 512>>>(trg, trg_emb, G.y);

    // ---------------- Encoder ----------------
    for (int i = 0; i < Nl; i++) {
        run_mha_self(G, G.x,
                G.encWh + (long long)i * 4 * DD2, G.encWl + (long long)i * 4 * DD2,
                G.tmp, false);
        add_ln_kernel<<<TOK, 256>>>(G.x, G.tmp);
        run_ffn(G, G.x,
                G.eW1h + (long long)i * W1SZ, G.eW1l + (long long)i * W1SZ,
                enc_ffn_b1 + (long long)i * FFf,
                G.eW2h + (long long)i * W1SZ, G.eW2l + (long long)i * W1SZ,
                enc_ffn_b2 + (long long)i * Dd);
        add_ln_kernel<<<TOK, 256>>>(G.x, G.tmp);
    }

    // pack encoder output; precompute ALL cross-attn K,V (6 layers) in one fat launch
    convAT<<<dim3(TOK/32, Dd/32), 256>>>(G.x, G.xeTh, G.xeTl, TOK, Dd);
    {
        dim3 g(TOK/64, Dd/64, 2 * Nl);
        gemm_ap<64,64,128,2,3,3><<<g, 128, SM_AP64_3>>>(G.xeTh, G.xeTl,
            G.decCWh + DD2, G.decCWl + DD2,
            nullptr, nullptr, G.xKVh, G.xKVl,
            Dd, TOK, Dd, TOK, Dd,
            0, 0, (long long)4 * DD2, DD2, (long long)2 * KVC, KVC,
            2, 1, 1.0f, 0, 0);
    }

    // ---------------- Decoder ----------------
    for (int i = 0; i < Nl; i++) {
        run_mha_self(G, G.y,
                G.decSWh + (long long)i * 4 * DD2, G.decSWl + (long long)i * 4 * DD2,
                G.tmp, true);
        add_ln_kernel<<<TOK, 256>>>(G.y, G.tmp);

        run_mha_cross(G, G.y, i,
                G.decCWh + (long long)i * 4 * DD2, G.decCWl + (long long)i * 4 * DD2,
                G.tmp);
        add_ln_kernel<<<TOK, 256>>>(G.y, G.tmp);

        run_ffn(G, G.y,
                G.dW1h + (long long)i * W1SZ, G.dW1l + (long long)i * W1SZ,
                dec_ffn_b1 + (long long)i * FFf,
                G.dW2h + (long long)i * W1SZ, G.dW2l + (long long)i * W1SZ,
                dec_ffn_b2 + (long long)i * Dd);
        add_ln_kernel<<<TOK, 256>>>(G.y, G.tmp);
    }

    // ---------------- Output projection + vocab softmax ----------------
    convAT<<<dim3(TOK/32, Dd/32), 256>>>(G.y, G.xTh, G.xTl, TOK, Dd);
    {
        dim3 g(TOK/128, Vv/128, 1);
        gemm_ap<128,128,256,4,3,0><<<g, 256, SM_AP128_3>>>(G.xTh, G.xTl, G.oWh, G.oWl,
            out_b, out, nullptr, nullptr,
            Dd, TOK, Vv, Vv, Dd,
            0, 0, 0, 0, 0, 0, 1, 0, 1.0f, 1, 0);
    }
    softmax_vocab<<<TOK, 1024>>>(out);
}